// round 4
// baseline (speedup 1.0000x reference)
#include <cuda_runtime.h>

#define NUM_CLASSES 8
#define EPS_SN 1e-5f
#define CB  16   // output channels per block
#define CCH 8    // input-channel chunk staged through smem

// ---------------- scratch (device globals; no allocation allowed) ------------
__device__ float g_bufA[67108864];   // 4*64*512*512 floats = 268 MB
__device__ float g_bufB[67108864];
__device__ float g_stats[16384];     // B*C*8 classes*2 (sum, sumsq), max C=256

// ---------------- packed fp32x2 helpers (sm_100+ PTX) ------------------------
__device__ __forceinline__ unsigned long long dup2(float v) {
    unsigned long long d;
    asm("mov.b64 %0, {%1, %1};" : "=l"(d) : "f"(v));
    return d;
}
__device__ __forceinline__ unsigned long long ffma2(unsigned long long a,
                                                    unsigned long long b,
                                                    unsigned long long c) {
    unsigned long long d;
    asm("fma.rn.f32x2 %0, %1, %2, %3;" : "=l"(d) : "l"(a), "l"(b), "l"(c));
    return d;
}
__device__ __forceinline__ void unpack2(unsigned long long a, float& lo, float& hi) {
    asm("mov.b64 {%0, %1}, %2;" : "=f"(lo), "=f"(hi) : "l"(a));
}

// ---------------- 3x3 conv, reflect pad 1, bias, optional relu ---------------
// Grid: (W/32, (H/8)*B, ceil(Cout/CB)), Block: (32,8).
// Each thread: 1 output pixel x CB couts (8 packed f32x2 accumulators).
__global__ __launch_bounds__(256) void conv3x3_kernel(
    const float* __restrict__ in, const float* __restrict__ wgt,
    const float* __restrict__ bias, float* __restrict__ out,
    int Cin, int Cout, int H, int W, int tilesY, int doRelu)
{
    __shared__ __align__(16) float s_in[CCH][10][34];
    __shared__ __align__(16) float s_w[CCH][9][CB];

    const int tx = threadIdx.x, ty = threadIdx.y;
    const int tid = ty * 32 + tx;
    const int tileY = blockIdx.y % tilesY;
    const int b     = blockIdx.y / tilesY;
    const int co0   = blockIdx.z * CB;
    const int x0 = blockIdx.x * 32, y0 = tileY * 8;

    unsigned long long acc[CB / 2];
#pragma unroll
    for (int p = 0; p < CB / 2; p++) acc[p] = 0ULL;

    const float* inB = in + (size_t)b * Cin * H * W;

    for (int cin0 = 0; cin0 < Cin; cin0 += CCH) {
        __syncthreads();
        // stage input tiles (10x34 with reflect halo) for CCH channels
        for (int i = tid; i < CCH * 340; i += 256) {
            int ci = i / 340; int rem = i - ci * 340;
            int r = rem / 34; int c = rem - r * 34;
            int gr = y0 - 1 + r;
            int gc = x0 - 1 + c;
            gr = (gr < 0) ? -gr : ((gr >= H) ? 2 * H - 2 - gr : gr);
            gc = (gc < 0) ? -gc : ((gc >= W) ? 2 * W - 2 - gc : gc);
            s_in[ci][r][c] = inB[(size_t)(cin0 + ci) * H * W + gr * W + gc];
        }
        // stage weights [ci][k][co_local], zero-fill past Cout
        for (int i = tid; i < CCH * 9 * CB; i += 256) {
            int ci = i / (9 * CB); int rem = i - ci * (9 * CB);
            int k = rem / CB; int j = rem - k * CB;
            int co = co0 + j;
            s_w[ci][k][j] = (co < Cout)
                ? wgt[((size_t)co * Cin + cin0 + ci) * 9 + k] : 0.f;
        }
        __syncthreads();

        for (int ci = 0; ci < CCH; ci++) {
            unsigned long long d[9];
#pragma unroll
            for (int r = 0; r < 3; r++)
#pragma unroll
                for (int c = 0; c < 3; c++)
                    d[r * 3 + c] = dup2(s_in[ci][ty + r][tx + c]);
#pragma unroll
            for (int k = 0; k < 9; k++) {
                const unsigned long long* wp =
                    (const unsigned long long*)&s_w[ci][k][0];
#pragma unroll
                for (int p = 0; p < CB / 2; p++)
                    acc[p] = ffma2(d[k], wp[p], acc[p]);
            }
        }
    }

    const int y = y0 + ty, x = x0 + tx;
#pragma unroll
    for (int p = 0; p < CB / 2; p++) {
        float lo, hi;
        unpack2(acc[p], lo, hi);
        int co = co0 + 2 * p;
        if (co < Cout) {
            float r = lo + bias[co];
            if (doRelu) r = fmaxf(r, 0.f);
            out[((size_t)(b * Cout + co) * H + y) * W + x] = r;
        }
        if (co + 1 < Cout) {
            float r = hi + bias[co + 1];
            if (doRelu) r = fmaxf(r, 0.f);
            out[((size_t)(b * Cout + co + 1) * H + y) * W + x] = r;
        }
    }
}

// ---------------- per-class instance-norm: pass 1 (stats) --------------------
// out[p] = x[p]*rs[class(p)] - sum_c mu_c*rs_c  (each pixel has exactly 1 class)
__global__ __launch_bounds__(256) void segnorm_stats(
    const float* __restrict__ x, const int* __restrict__ seg,
    float* __restrict__ stats, int C, int HW, int logW, int sh)
{
    const int bc = blockIdx.x;
    const int b = bc / C;
    const float* xp = x + (size_t)bc * HW;
    const int* sp = seg + b * 4096;
    const int Wm1 = (1 << logW) - 1;

    float s[8] = {0, 0, 0, 0, 0, 0, 0, 0};
    float q[8] = {0, 0, 0, 0, 0, 0, 0, 0};
    for (int i = threadIdx.x; i < HW; i += 256) {
        int h = i >> logW, wd = i & Wm1;
        int cls = sp[((h >> sh) << 6) + (wd >> sh)];
        float v = xp[i];
        float v2 = v * v;
#pragma unroll
        for (int k = 0; k < 8; k++)
            if (cls == k) { s[k] += v; q[k] += v2; }
    }
#pragma unroll
    for (int k = 0; k < 8; k++) {
#pragma unroll
        for (int o = 16; o > 0; o >>= 1) {
            s[k] += __shfl_xor_sync(0xffffffffu, s[k], o);
            q[k] += __shfl_xor_sync(0xffffffffu, q[k], o);
        }
    }
    __shared__ float shs[8][8], shq[8][8];
    int warp = threadIdx.x >> 5, lane = threadIdx.x & 31;
    if (lane == 0) {
#pragma unroll
        for (int k = 0; k < 8; k++) { shs[warp][k] = s[k]; shq[warp][k] = q[k]; }
    }
    __syncthreads();
    if (threadIdx.x < 8) {
        float S = 0, Q = 0;
#pragma unroll
        for (int wpi = 0; wpi < 8; wpi++) { S += shs[wpi][threadIdx.x]; Q += shq[wpi][threadIdx.x]; }
        stats[bc * 16 + threadIdx.x * 2]     = S;
        stats[bc * 16 + threadIdx.x * 2 + 1] = Q;
    }
}

// ---------------- per-class instance-norm: pass 2 (apply) --------------------
__global__ __launch_bounds__(256) void segnorm_apply(
    const float* __restrict__ x, const int* __restrict__ seg,
    const float* __restrict__ stats, float* __restrict__ out,
    int C, int HW, int logW, int sh, int pxPerChunk, float invHW)
{
    const int bc = blockIdx.x;
    const int b = bc / C;
    __shared__ float s_rs[8], s_muR[8];
    if (threadIdx.x < 8) {
        float S = stats[bc * 16 + threadIdx.x * 2];
        float Q = stats[bc * 16 + threadIdx.x * 2 + 1];
        float mu = S * invHW;
        float var = Q * invHW - mu * mu;
        float r = rsqrtf(var + EPS_SN);
        s_rs[threadIdx.x]  = r;
        s_muR[threadIdx.x] = mu * r;
    }
    __syncthreads();
    float K = 0.f;
#pragma unroll
    for (int k = 0; k < 8; k++) K += s_muR[k];

    const float* xp = x + (size_t)bc * HW;
    float* op = out + (size_t)bc * HW;
    const int* sp = seg + b * 4096;
    const int Wm1 = (1 << logW) - 1;
    const int end = min(HW, (int)((blockIdx.y + 1) * pxPerChunk));
    for (int i = blockIdx.y * pxPerChunk + threadIdx.x; i < end; i += 256) {
        int h = i >> logW, wd = i & Wm1;
        int cls = sp[((h >> sh) << 6) + (wd >> sh)];
        op[i] = xp[i] * s_rs[cls] - K;
    }
}

// ---------------- bilinear 2x upsample (half-pixel, edge clamp) --------------
__global__ __launch_bounds__(256) void up2_kernel(
    const float* __restrict__ in, float* __restrict__ out,
    int BC, int Hin, int Win)
{
    const int Ho = Hin * 2, Wo = Win * 2;
    const int total = BC * Ho * Wo;
    int i = blockIdx.x * 256 + threadIdx.x;
    if (i >= total) return;
    int xo = i % Wo;
    int t  = i / Wo;
    int yo = t % Ho;
    int bc = t / Ho;

    int iy = yo >> 1, ix = xo >> 1;
    int y0, y1, x0c, x1c;
    float wy0, wy1, wx0, wx1;
    if (yo & 1) { y0 = iy; y1 = min(iy + 1, Hin - 1); wy0 = 0.75f; wy1 = 0.25f; }
    else        { y0 = max(iy - 1, 0); y1 = iy;       wy0 = 0.25f; wy1 = 0.75f; }
    if (xo & 1) { x0c = ix; x1c = min(ix + 1, Win - 1); wx0 = 0.75f; wx1 = 0.25f; }
    else        { x0c = max(ix - 1, 0); x1c = ix;       wx0 = 0.25f; wx1 = 0.75f; }

    const float* p = in + (size_t)bc * Hin * Win;
    float v = wy0 * (wx0 * p[y0 * Win + x0c] + wx1 * p[y0 * Win + x1c])
            + wy1 * (wx0 * p[y1 * Win + x0c] + wx1 * p[y1 * Win + x1c]);
    out[i] = v;
}

// ---------------- host-side orchestration ------------------------------------
static inline int ilog2i(int v) { int l = 0; while ((1 << l) < v) l++; return l; }

static inline void launch_conv(const float* in, const float* w, const float* b,
                               float* out, int B, int Cin, int Cout, int H, int Wd,
                               int relu) {
    dim3 grid(Wd / 32, (H / 8) * B, (Cout + CB - 1) / CB);
    conv3x3_kernel<<<grid, dim3(32, 8)>>>(in, w, b, out, Cin, Cout, H, Wd, H / 8, relu);
}

static inline void launch_segnorm(const float* in, const int* seg, float* stats,
                                  float* out, int B, int C, int H, int W) {
    int HW = H * W;
    int logW = ilog2i(W);
    int sh = ilog2i(H / 64);   // seg is 64x64: src = h >> sh
    segnorm_stats<<<B * C, 256>>>(in, seg, stats, C, HW, logW, sh);
    int chunks = (HW > 16384) ? (HW >> 14) : 1;
    int px = HW / chunks;
    segnorm_apply<<<dim3(B * C, chunks), 256>>>(in, seg, stats, out, C, HW, logW,
                                                sh, px, 1.0f / (float)HW);
}

static inline void launch_up2(const float* in, float* out, int BC, int Hin, int Win) {
    int total = BC * 4 * Hin * Win;
    up2_kernel<<<(total + 255) / 256, 256>>>(in, out, BC, Hin, Win);
}

extern "C" void kernel_launch(void* const* d_in, const int* in_sizes, int n_in,
                              void* d_out, int out_size) {
    const float* x   = (const float*)d_in[0];
    const int*   seg = (const int*)  d_in[1];
    const float* w1 = (const float*)d_in[2];   const float* b1 = (const float*)d_in[3];
    const float* w2 = (const float*)d_in[4];   const float* b2 = (const float*)d_in[5];
    const float* w3 = (const float*)d_in[6];   const float* b3 = (const float*)d_in[7];
    const float* w4 = (const float*)d_in[8];   const float* b4 = (const float*)d_in[9];
    const float* w5 = (const float*)d_in[10];  const float* b5 = (const float*)d_in[11];
    const float* w6 = (const float*)d_in[12];  const float* b6 = (const float*)d_in[13];
    const float* w7 = (const float*)d_in[14];  const float* b7 = (const float*)d_in[15];
    const float* w8 = (const float*)d_in[16];  const float* b8 = (const float*)d_in[17];
    const float* wf = (const float*)d_in[18];  const float* bf = (const float*)d_in[19];

    float *A, *Bb, *st;
    cudaGetSymbolAddress((void**)&A,  g_bufA);
    cudaGetSymbolAddress((void**)&Bb, g_bufB);
    cudaGetSymbolAddress((void**)&st, g_stats);

    // stage 1 @ 64x64
    launch_conv(x, w1, b1, A, 4, 512, 256, 64, 64, 1);
    launch_segnorm(A, seg, st, Bb, 4, 256, 64, 64);
    launch_up2(Bb, A, 4 * 256, 64, 64);            // -> 128x128

    // stage 2 @ 128x128
    launch_conv(A,  w2, b2, Bb, 4, 256, 256, 128, 128, 1);
    launch_conv(Bb, w3, b3, A,  4, 256, 256, 128, 128, 1);
    launch_conv(A,  w4, b4, Bb, 4, 256, 256, 128, 128, 1);
    launch_conv(Bb, w5, b5, A,  4, 256, 128, 128, 128, 1);
    launch_segnorm(A, seg, st, Bb, 4, 128, 128, 128);
    launch_up2(Bb, A, 4 * 128, 128, 128);          // -> 256x256

    // stage 3 @ 256x256
    launch_conv(A,  w6, b6, Bb, 4, 128, 128, 256, 256, 1);
    launch_conv(Bb, w7, b7, A,  4, 128, 64, 256, 256, 1);
    launch_segnorm(A, seg, st, Bb, 4, 64, 256, 256);
    launch_up2(Bb, A, 4 * 64, 256, 256);           // -> 512x512

    // stage 4 @ 512x512
    launch_conv(A,  w8, b8, Bb, 4, 64, 64, 512, 512, 1);
    launch_conv(Bb, wf, bf, (float*)d_out, 4, 64, 3, 512, 512, 0);  // no relu
}

// round 8
// speedup vs baseline: 1.0299x; 1.0299x over previous
#include <cuda_runtime.h>

#define NUM_CLASSES 8
#define EPS_SN 1e-5f
#define CB  8    // output channels per block
#define CCH 8    // input-channel chunk staged through smem
#define PY  4    // pixels per thread (stacked in y)

// ---------------- scratch (device globals; no allocation allowed) ------------
__device__ float g_bufA[67108864];   // 4*64*512*512 floats = 268 MB
__device__ float g_bufB[67108864];
__device__ float g_stats[16384];     // B*C*8 classes*2 (sum, sumsq), max C=256

// ---------------- packed fp32x2 helpers (sm_100+ PTX) ------------------------
__device__ __forceinline__ unsigned long long dup2(float v) {
    unsigned long long d;
    asm("mov.b64 %0, {%1, %1};" : "=l"(d) : "f"(v));
    return d;
}
__device__ __forceinline__ unsigned long long ffma2(unsigned long long a,
                                                    unsigned long long b,
                                                    unsigned long long c) {
    unsigned long long d;
    asm("fma.rn.f32x2 %0, %1, %2, %3;" : "=l"(d) : "l"(a), "l"(b), "l"(c));
    return d;
}
__device__ __forceinline__ void unpack2(unsigned long long a, float& lo, float& hi) {
    asm("mov.b64 {%0, %1}, %2;" : "=f"(lo), "=f"(hi) : "l"(a));
}

// ---------------- 3x3 conv, reflect pad 1, bias, optional relu ---------------
// Grid: (W/32, (H/32)*B, ceil(Cout/CB)), Block: (32,8).
// Thread: PY=4 stacked pixels x CB=8 couts -> 16 packed f32x2 accumulators.
// Per cin channel per thread: 18 input LDS + 36 weight LDS.64 -> 144 FFMA2.
__global__ __launch_bounds__(256) void conv3x3_kernel(
    const float* __restrict__ in, const float* __restrict__ wgt,
    const float* __restrict__ bias, float* __restrict__ out,
    int Cin, int Cout, int H, int W, int tilesY, int doRelu)
{
    __shared__ __align__(16) float s_in[CCH][34][34];
    __shared__ __align__(16) float s_w[CCH][9][CB];

    const int tx = threadIdx.x, ty = threadIdx.y;
    const int tid = ty * 32 + tx;
    const int tileY = blockIdx.y % tilesY;
    const int b     = blockIdx.y / tilesY;
    const int co0   = blockIdx.z * CB;
    const int x0 = blockIdx.x * 32, y0 = tileY * 32;

    unsigned long long acc[PY][CB / 2];
#pragma unroll
    for (int p = 0; p < PY; p++)
#pragma unroll
        for (int j = 0; j < CB / 2; j++) acc[p][j] = 0ULL;

    const float* inB = in + (size_t)b * Cin * H * W;

    for (int cin0 = 0; cin0 < Cin; cin0 += CCH) {
        __syncthreads();
        // stage input tiles (34x34 with reflect halo) for CCH channels
        for (int i = tid; i < CCH * 1156; i += 256) {
            int ci = i / 1156; int rem = i - ci * 1156;
            int r = rem / 34; int c = rem - r * 34;
            int gr = y0 - 1 + r;
            int gc = x0 - 1 + c;
            gr = (gr < 0) ? -gr : ((gr >= H) ? 2 * H - 2 - gr : gr);
            gc = (gc < 0) ? -gc : ((gc >= W) ? 2 * W - 2 - gc : gc);
            s_in[ci][r][c] = inB[(size_t)(cin0 + ci) * H * W + gr * W + gc];
        }
        // stage weights [ci][k][co_local], zero-fill past Cout
        for (int i = tid; i < CCH * 9 * CB; i += 256) {
            int ci = i / (9 * CB); int rem = i - ci * (9 * CB);
            int k = rem / CB; int j = rem - k * CB;
            int co = co0 + j;
            s_w[ci][k][j] = (co < Cout)
                ? wgt[((size_t)co * Cin + cin0 + ci) * 9 + k] : 0.f;
        }
        __syncthreads();

#pragma unroll 1
        for (int ci = 0; ci < CCH; ci++) {
            // 6 rows x 3 cols of duplicated input values cover all 9 taps
            // for the 4 stacked output pixels.
            unsigned long long dp[6][3];
#pragma unroll
            for (int rr = 0; rr < 6; rr++)
#pragma unroll
                for (int c = 0; c < 3; c++)
                    dp[rr][c] = dup2(s_in[ci][ty * PY + rr][tx + c]);

#pragma unroll
            for (int kr = 0; kr < 3; kr++) {
#pragma unroll
                for (int kc = 0; kc < 3; kc++) {
                    const unsigned long long* wp =
                        (const unsigned long long*)&s_w[ci][kr * 3 + kc][0];
                    unsigned long long w0 = wp[0], w1 = wp[1],
                                       w2 = wp[2], w3 = wp[3];
#pragma unroll
                    for (int p = 0; p < PY; p++) {
                        unsigned long long d = dp[kr + p][kc];
                        acc[p][0] = ffma2(d, w0, acc[p][0]);
                        acc[p][1] = ffma2(d, w1, acc[p][1]);
                        acc[p][2] = ffma2(d, w2, acc[p][2]);
                        acc[p][3] = ffma2(d, w3, acc[p][3]);
                    }
                }
            }
        }
    }

    const int x = x0 + tx;
    const int yBase = y0 + ty * PY;
#pragma unroll
    for (int p = 0; p < PY; p++) {
        const int y = yBase + p;
#pragma unroll
        for (int j = 0; j < CB / 2; j++) {
            float lo, hi;
            unpack2(acc[p][j], lo, hi);
            int co = co0 + 2 * j;
            if (co < Cout) {
                float r = lo + bias[co];
                if (doRelu) r = fmaxf(r, 0.f);
                out[((size_t)(b * Cout + co) * H + y) * W + x] = r;
            }
            if (co + 1 < Cout) {
                float r = hi + bias[co + 1];
                if (doRelu) r = fmaxf(r, 0.f);
                out[((size_t)(b * Cout + co + 1) * H + y) * W + x] = r;
            }
        }
    }
}

// ---------------- per-class instance-norm: pass 1 (stats) --------------------
// out[p] = x[p]*rs[class(p)] - sum_c mu_c*rs_c  (each pixel has exactly 1 class)
__global__ __launch_bounds__(256) void segnorm_stats(
    const float* __restrict__ x, const int* __restrict__ seg,
    float* __restrict__ stats, int C, int HW, int logW, int sh)
{
    const int bc = blockIdx.x;
    const int b = bc / C;
    const float* xp = x + (size_t)bc * HW;
    const int* sp = seg + b * 4096;
    const int Wm1 = (1 << logW) - 1;

    float s[8] = {0, 0, 0, 0, 0, 0, 0, 0};
    float q[8] = {0, 0, 0, 0, 0, 0, 0, 0};
    for (int i = threadIdx.x; i < HW; i += 256) {
        int h = i >> logW, wd = i & Wm1;
        int cls = sp[((h >> sh) << 6) + (wd >> sh)];
        float v = xp[i];
        float v2 = v * v;
#pragma unroll
        for (int k = 0; k < 8; k++)
            if (cls == k) { s[k] += v; q[k] += v2; }
    }
#pragma unroll
    for (int k = 0; k < 8; k++) {
#pragma unroll
        for (int o = 16; o > 0; o >>= 1) {
            s[k] += __shfl_xor_sync(0xffffffffu, s[k], o);
            q[k] += __shfl_xor_sync(0xffffffffu, q[k], o);
        }
    }
    __shared__ float shs[8][8], shq[8][8];
    int warp = threadIdx.x >> 5, lane = threadIdx.x & 31;
    if (lane == 0) {
#pragma unroll
        for (int k = 0; k < 8; k++) { shs[warp][k] = s[k]; shq[warp][k] = q[k]; }
    }
    __syncthreads();
    if (threadIdx.x < 8) {
        float S = 0, Q = 0;
#pragma unroll
        for (int wpi = 0; wpi < 8; wpi++) { S += shs[wpi][threadIdx.x]; Q += shq[wpi][threadIdx.x]; }
        stats[bc * 16 + threadIdx.x * 2]     = S;
        stats[bc * 16 + threadIdx.x * 2 + 1] = Q;
    }
}

// ---------------- per-class instance-norm: pass 2 (apply) --------------------
__global__ __launch_bounds__(256) void segnorm_apply(
    const float* __restrict__ x, const int* __restrict__ seg,
    const float* __restrict__ stats, float* __restrict__ out,
    int C, int HW, int logW, int sh, int pxPerChunk, float invHW)
{
    const int bc = blockIdx.x;
    const int b = bc / C;
    __shared__ float s_rs[8], s_muR[8];
    if (threadIdx.x < 8) {
        float S = stats[bc * 16 + threadIdx.x * 2];
        float Q = stats[bc * 16 + threadIdx.x * 2 + 1];
        float mu = S * invHW;
        float var = Q * invHW - mu * mu;
        float r = rsqrtf(var + EPS_SN);
        s_rs[threadIdx.x]  = r;
        s_muR[threadIdx.x] = mu * r;
    }
    __syncthreads();
    float K = 0.f;
#pragma unroll
    for (int k = 0; k < 8; k++) K += s_muR[k];

    const float* xp = x + (size_t)bc * HW;
    float* op = out + (size_t)bc * HW;
    const int* sp = seg + b * 4096;
    const int Wm1 = (1 << logW) - 1;
    const int end = min(HW, (int)((blockIdx.y + 1) * pxPerChunk));
    for (int i = blockIdx.y * pxPerChunk + threadIdx.x; i < end; i += 256) {
        int h = i >> logW, wd = i & Wm1;
        int cls = sp[((h >> sh) << 6) + (wd >> sh)];
        op[i] = xp[i] * s_rs[cls] - K;
    }
}

// ---------------- bilinear 2x upsample (half-pixel, edge clamp) --------------
// 2 x-adjacent outputs per thread, pow2 shifts, float2 store.
__global__ __launch_bounds__(256) void up2_kernel(
    const float* __restrict__ in, float* __restrict__ out,
    int BC, int Hin, int Win, int logWin, int logHo)
{
    const int Ho = Hin * 2, Wo = Win * 2;
    const int total = BC << (logWin + logHo);   // BC * Ho * Win
    int i = blockIdx.x * 256 + threadIdx.x;
    if (i >= total) return;
    int ix = i & (Win - 1);
    int t  = i >> logWin;
    int yo = t & (Ho - 1);
    int bc = t >> logHo;

    int iy = yo >> 1;
    int y0, y1;
    float wy0, wy1;
    if (yo & 1) { y0 = iy; y1 = min(iy + 1, Hin - 1); wy0 = 0.75f; wy1 = 0.25f; }
    else        { y0 = max(iy - 1, 0); y1 = iy;       wy0 = 0.25f; wy1 = 0.75f; }
    int xm = max(ix - 1, 0), xp = min(ix + 1, Win - 1);

    const float* p = in + (size_t)bc * Hin * Win;
    const float* r0 = p + y0 * Win;
    const float* r1 = p + y1 * Win;
    float am = r0[xm], a0 = r0[ix], ap = r0[xp];
    float bm = r1[xm], b0 = r1[ix], bp = r1[xp];

    float2 v;
    v.x = wy0 * (0.25f * am + 0.75f * a0) + wy1 * (0.25f * bm + 0.75f * b0);
    v.y = wy0 * (0.75f * a0 + 0.25f * ap) + wy1 * (0.75f * b0 + 0.25f * bp);
    *(float2*)(out + ((size_t)bc * Ho + yo) * Wo + 2 * ix) = v;
}

// ---------------- host-side orchestration ------------------------------------
static inline int ilog2i(int v) { int l = 0; while ((1 << l) < v) l++; return l; }

static inline void launch_conv(const float* in, const float* w, const float* b,
                               float* out, int B, int Cin, int Cout, int H, int Wd,
                               int relu) {
    dim3 grid(Wd / 32, (H / 32) * B, (Cout + CB - 1) / CB);
    conv3x3_kernel<<<grid, dim3(32, 8)>>>(in, w, b, out, Cin, Cout, H, Wd, H / 32, relu);
}

static inline void launch_segnorm(const float* in, const int* seg, float* stats,
                                  float* out, int B, int C, int H, int W) {
    int HW = H * W;
    int logW = ilog2i(W);
    int sh = ilog2i(H / 64);   // seg is 64x64: src = h >> sh
    segnorm_stats<<<B * C, 256>>>(in, seg, stats, C, HW, logW, sh);
    int chunks = (HW > 16384) ? (HW >> 14) : 1;
    int px = HW / chunks;
    segnorm_apply<<<dim3(B * C, chunks), 256>>>(in, seg, stats, out, C, HW, logW,
                                                sh, px, 1.0f / (float)HW);
}

static inline void launch_up2(const float* in, float* out, int BC, int Hin, int Win) {
    int total = BC * 2 * Hin * Win;   // one thread per 2 output pixels
    up2_kernel<<<(total + 255) / 256, 256>>>(in, out, BC, Hin, Win,
                                             ilog2i(Win), ilog2i(2 * Hin));
}

extern "C" void kernel_launch(void* const* d_in, const int* in_sizes, int n_in,
                              void* d_out, int out_size) {
    const float* x   = (const float*)d_in[0];
    const int*   seg = (const int*)  d_in[1];
    const float* w1 = (const float*)d_in[2];   const float* b1 = (const float*)d_in[3];
    const float* w2 = (const float*)d_in[4];   const float* b2 = (const float*)d_in[5];
    const float* w3 = (const float*)d_in[6];   const float* b3 = (const float*)d_in[7];
    const float* w4 = (const float*)d_in[8];   const float* b4 = (const float*)d_in[9];
    const float* w5 = (const float*)d_in[10];  const float* b5 = (const float*)d_in[11];
    const float* w6 = (const float*)d_in[12];  const float* b6 = (const float*)d_in[13];
    const float* w7 = (const float*)d_in[14];  const float* b7 = (const float*)d_in[15];
    const float* w8 = (const float*)d_in[16];  const float* b8 = (const float*)d_in[17];
    const float* wf = (const float*)d_in[18];  const float* bf = (const float*)d_in[19];

    float *A, *Bb, *st;
    cudaGetSymbolAddress((void**)&A,  g_bufA);
    cudaGetSymbolAddress((void**)&Bb, g_bufB);
    cudaGetSymbolAddress((void**)&st, g_stats);

    // stage 1 @ 64x64
    launch_conv(x, w1, b1, A, 4, 512, 256, 64, 64, 1);
    launch_segnorm(A, seg, st, Bb, 4, 256, 64, 64);
    launch_up2(Bb, A, 4 * 256, 64, 64);            // -> 128x128

    // stage 2 @ 128x128
    launch_conv(A,  w2, b2, Bb, 4, 256, 256, 128, 128, 1);
    launch_conv(Bb, w3, b3, A,  4, 256, 256, 128, 128, 1);
    launch_conv(A,  w4, b4, Bb, 4, 256, 256, 128, 128, 1);
    launch_conv(Bb, w5, b5, A,  4, 256, 128, 128, 128, 1);
    launch_segnorm(A, seg, st, Bb, 4, 128, 128, 128);
    launch_up2(Bb, A, 4 * 128, 128, 128);          // -> 256x256

    // stage 3 @ 256x256
    launch_conv(A,  w6, b6, Bb, 4, 128, 128, 256, 256, 1);
    launch_conv(Bb, w7, b7, A,  4, 128, 64, 256, 256, 1);
    launch_segnorm(A, seg, st, Bb, 4, 64, 256, 256);
    launch_up2(Bb, A, 4 * 64, 256, 256);           // -> 512x512

    // stage 4 @ 512x512
    launch_conv(A,  w8, b8, Bb, 4, 64, 64, 512, 512, 1);
    launch_conv(Bb, wf, bf, (float*)d_out, 4, 64, 3, 512, 512, 0);  // no relu
}

// round 9
// speedup vs baseline: 1.0338x; 1.0038x over previous
#include <cuda_runtime.h>

#define NUM_CLASSES 8
#define EPS_SN 1e-5f
#define CB  8    // output channels per block
#define CCH 8    // input-channel chunk staged through smem
#define PY  4    // pixels per thread (stacked in y)

// ---------------- scratch (device globals; no allocation allowed) ------------
__device__ float g_bufA[67108864];   // 4*64*512*512 floats = 268 MB
__device__ float g_bufB[67108864];
__device__ float g_stats[16384];     // B*C*8 classes*2 (sum, sumsq), max C=256

// ---------------- packed fp32x2 helpers (sm_100+ PTX) ------------------------
__device__ __forceinline__ unsigned long long dup2(float v) {
    unsigned long long d;
    asm("mov.b64 %0, {%1, %1};" : "=l"(d) : "f"(v));
    return d;
}
__device__ __forceinline__ unsigned long long ffma2(unsigned long long a,
                                                    unsigned long long b,
                                                    unsigned long long c) {
    unsigned long long d;
    asm("fma.rn.f32x2 %0, %1, %2, %3;" : "=l"(d) : "l"(a), "l"(b), "l"(c));
    return d;
}
__device__ __forceinline__ void unpack2(unsigned long long a, float& lo, float& hi) {
    asm("mov.b64 {%0, %1}, %2;" : "=f"(lo), "=f"(hi) : "l"(a));
}

// ---------------- 3x3 conv, reflect pad 1, bias, optional relu ---------------
// Grid: (W/32, (H/32)*B, ceil(Cout/CB)), Block: (32,8).
// Thread: PY=4 stacked pixels x CB=8 couts -> 16 packed f32x2 accumulators.
// Per cin channel per thread: 18 input LDS + 36 weight LDS.64 -> 144 FFMA2.
__global__ __launch_bounds__(256) void conv3x3_kernel(
    const float* __restrict__ in, const float* __restrict__ wgt,
    const float* __restrict__ bias, float* __restrict__ out,
    int Cin, int Cout, int H, int W, int tilesY, int doRelu)
{
    __shared__ __align__(16) float s_in[CCH][34][34];
    __shared__ __align__(16) float s_w[CCH][9][CB];

    const int tx = threadIdx.x, ty = threadIdx.y;
    const int tid = ty * 32 + tx;
    const int tileY = blockIdx.y % tilesY;
    const int b     = blockIdx.y / tilesY;
    const int co0   = blockIdx.z * CB;
    const int x0 = blockIdx.x * 32, y0 = tileY * 32;

    unsigned long long acc[PY][CB / 2];
#pragma unroll
    for (int p = 0; p < PY; p++)
#pragma unroll
        for (int j = 0; j < CB / 2; j++) acc[p][j] = 0ULL;

    const float* inB = in + (size_t)b * Cin * H * W;

    for (int cin0 = 0; cin0 < Cin; cin0 += CCH) {
        __syncthreads();
        // stage input tiles (34x34 with reflect halo) for CCH channels
        for (int i = tid; i < CCH * 1156; i += 256) {
            int ci = i / 1156; int rem = i - ci * 1156;
            int r = rem / 34; int c = rem - r * 34;
            int gr = y0 - 1 + r;
            int gc = x0 - 1 + c;
            gr = (gr < 0) ? -gr : ((gr >= H) ? 2 * H - 2 - gr : gr);
            gc = (gc < 0) ? -gc : ((gc >= W) ? 2 * W - 2 - gc : gc);
            s_in[ci][r][c] = inB[(size_t)(cin0 + ci) * H * W + gr * W + gc];
        }
        // stage weights [ci][k][co_local], zero-fill past Cout
        for (int i = tid; i < CCH * 9 * CB; i += 256) {
            int ci = i / (9 * CB); int rem = i - ci * (9 * CB);
            int k = rem / CB; int j = rem - k * CB;
            int co = co0 + j;
            s_w[ci][k][j] = (co < Cout)
                ? wgt[((size_t)co * Cin + cin0 + ci) * 9 + k] : 0.f;
        }
        __syncthreads();

#pragma unroll 1
        for (int ci = 0; ci < CCH; ci++) {
            // 6 rows x 3 cols of duplicated input values cover all 9 taps
            // for the 4 stacked output pixels.
            unsigned long long dp[6][3];
#pragma unroll
            for (int rr = 0; rr < 6; rr++)
#pragma unroll
                for (int c = 0; c < 3; c++)
                    dp[rr][c] = dup2(s_in[ci][ty * PY + rr][tx + c]);

#pragma unroll
            for (int kr = 0; kr < 3; kr++) {
#pragma unroll
                for (int kc = 0; kc < 3; kc++) {
                    const unsigned long long* wp =
                        (const unsigned long long*)&s_w[ci][kr * 3 + kc][0];
                    unsigned long long w0 = wp[0], w1 = wp[1],
                                       w2 = wp[2], w3 = wp[3];
#pragma unroll
                    for (int p = 0; p < PY; p++) {
                        unsigned long long d = dp[kr + p][kc];
                        acc[p][0] = ffma2(d, w0, acc[p][0]);
                        acc[p][1] = ffma2(d, w1, acc[p][1]);
                        acc[p][2] = ffma2(d, w2, acc[p][2]);
                        acc[p][3] = ffma2(d, w3, acc[p][3]);
                    }
                }
            }
        }
    }

    const int x = x0 + tx;
    const int yBase = y0 + ty * PY;
#pragma unroll
    for (int p = 0; p < PY; p++) {
        const int y = yBase + p;
#pragma unroll
        for (int j = 0; j < CB / 2; j++) {
            float lo, hi;
            unpack2(acc[p][j], lo, hi);
            int co = co0 + 2 * j;
            if (co < Cout) {
                float r = lo + bias[co];
                if (doRelu) r = fmaxf(r, 0.f);
                out[((size_t)(b * Cout + co) * H + y) * W + x] = r;
            }
            if (co + 1 < Cout) {
                float r = hi + bias[co + 1];
                if (doRelu) r = fmaxf(r, 0.f);
                out[((size_t)(b * Cout + co + 1) * H + y) * W + x] = r;
            }
        }
    }
}

// ---------------- per-class instance-norm: pass 1 (stats) --------------------
// out[p] = x[p]*rs[class(p)] - sum_c mu_c*rs_c  (each pixel has exactly 1 class)
__global__ __launch_bounds__(256) void segnorm_stats(
    const float* __restrict__ x, const int* __restrict__ seg,
    float* __restrict__ stats, int C, int HW, int logW, int sh)
{
    const int bc = blockIdx.x;
    const int b = bc / C;
    const float* xp = x + (size_t)bc * HW;
    const int* sp = seg + b * 4096;
    const int Wm1 = (1 << logW) - 1;

    float s[8] = {0, 0, 0, 0, 0, 0, 0, 0};
    float q[8] = {0, 0, 0, 0, 0, 0, 0, 0};
    for (int i = threadIdx.x; i < HW; i += 256) {
        int h = i >> logW, wd = i & Wm1;
        int cls = sp[((h >> sh) << 6) + (wd >> sh)];
        float v = xp[i];
        float v2 = v * v;
#pragma unroll
        for (int k = 0; k < 8; k++)
            if (cls == k) { s[k] += v; q[k] += v2; }
    }
#pragma unroll
    for (int k = 0; k < 8; k++) {
#pragma unroll
        for (int o = 16; o > 0; o >>= 1) {
            s[k] += __shfl_xor_sync(0xffffffffu, s[k], o);
            q[k] += __shfl_xor_sync(0xffffffffu, q[k], o);
        }
    }
    __shared__ float shs[8][8], shq[8][8];
    int warp = threadIdx.x >> 5, lane = threadIdx.x & 31;
    if (lane == 0) {
#pragma unroll
        for (int k = 0; k < 8; k++) { shs[warp][k] = s[k]; shq[warp][k] = q[k]; }
    }
    __syncthreads();
    if (threadIdx.x < 8) {
        float S = 0, Q = 0;
#pragma unroll
        for (int wpi = 0; wpi < 8; wpi++) { S += shs[wpi][threadIdx.x]; Q += shq[wpi][threadIdx.x]; }
        stats[bc * 16 + threadIdx.x * 2]     = S;
        stats[bc * 16 + threadIdx.x * 2 + 1] = Q;
    }
}

// ---------------- per-class instance-norm: pass 2 (apply) --------------------
__global__ __launch_bounds__(256) void segnorm_apply(
    const float* __restrict__ x, const int* __restrict__ seg,
    const float* __restrict__ stats, float* __restrict__ out,
    int C, int HW, int logW, int sh, int pxPerChunk, float invHW)
{
    const int bc = blockIdx.x;
    const int b = bc / C;
    __shared__ float s_rs[8], s_muR[8];
    if (threadIdx.x < 8) {
        float S = stats[bc * 16 + threadIdx.x * 2];
        float Q = stats[bc * 16 + threadIdx.x * 2 + 1];
        float mu = S * invHW;
        float var = Q * invHW - mu * mu;
        float r = rsqrtf(var + EPS_SN);
        s_rs[threadIdx.x]  = r;
        s_muR[threadIdx.x] = mu * r;
    }
    __syncthreads();
    float K = 0.f;
#pragma unroll
    for (int k = 0; k < 8; k++) K += s_muR[k];

    const float* xp = x + (size_t)bc * HW;
    float* op = out + (size_t)bc * HW;
    const int* sp = seg + b * 4096;
    const int Wm1 = (1 << logW) - 1;
    const int end = min(HW, (int)((blockIdx.y + 1) * pxPerChunk));
    for (int i = blockIdx.y * pxPerChunk + threadIdx.x; i < end; i += 256) {
        int h = i >> logW, wd = i & Wm1;
        int cls = sp[((h >> sh) << 6) + (wd >> sh)];
        op[i] = xp[i] * s_rs[cls] - K;
    }
}

// ---------------- bilinear 2x upsample (half-pixel, edge clamp) --------------
// 2 x-adjacent outputs per thread, pow2 shifts, float2 store.
__global__ __launch_bounds__(256) void up2_kernel(
    const float* __restrict__ in, float* __restrict__ out,
    int BC, int Hin, int Win, int logWin, int logHo)
{
    const int Ho = Hin * 2, Wo = Win * 2;
    const int total = BC << (logWin + logHo);   // BC * Ho * Win
    int i = blockIdx.x * 256 + threadIdx.x;
    if (i >= total) return;
    int ix = i & (Win - 1);
    int t  = i >> logWin;
    int yo = t & (Ho - 1);
    int bc = t >> logHo;

    int iy = yo >> 1;
    int y0, y1;
    float wy0, wy1;
    if (yo & 1) { y0 = iy; y1 = min(iy + 1, Hin - 1); wy0 = 0.75f; wy1 = 0.25f; }
    else        { y0 = max(iy - 1, 0); y1 = iy;       wy0 = 0.25f; wy1 = 0.75f; }
    int xm = max(ix - 1, 0), xp = min(ix + 1, Win - 1);

    const float* p = in + (size_t)bc * Hin * Win;
    const float* r0 = p + y0 * Win;
    const float* r1 = p + y1 * Win;
    float am = r0[xm], a0 = r0[ix], ap = r0[xp];
    float bm = r1[xm], b0 = r1[ix], bp = r1[xp];

    float2 v;
    v.x = wy0 * (0.25f * am + 0.75f * a0) + wy1 * (0.25f * bm + 0.75f * b0);
    v.y = wy0 * (0.75f * a0 + 0.25f * ap) + wy1 * (0.75f * b0 + 0.25f * bp);
    *(float2*)(out + ((size_t)bc * Ho + yo) * Wo + 2 * ix) = v;
}

// ---------------- host-side orchestration ------------------------------------
static inline int ilog2i(int v) { int l = 0; while ((1 << l) < v) l++; return l; }

static inline void launch_conv(const float* in, const float* w, const float* b,
                               float* out, int B, int Cin, int Cout, int H, int Wd,
                               int relu) {
    dim3 grid(Wd / 32, (H / 32) * B, (Cout + CB - 1) / CB);
    conv3x3_kernel<<<grid, dim3(32, 8)>>>(in, w, b, out, Cin, Cout, H, Wd, H / 32, relu);
}

static inline void launch_segnorm(const float* in, const int* seg, float* stats,
                                  float* out, int B, int C, int H, int W) {
    int HW = H * W;
    int logW = ilog2i(W);
    int sh = ilog2i(H / 64);   // seg is 64x64: src = h >> sh
    segnorm_stats<<<B * C, 256>>>(in, seg, stats, C, HW, logW, sh);
    int chunks = (HW > 16384) ? (HW >> 14) : 1;
    int px = HW / chunks;
    segnorm_apply<<<dim3(B * C, chunks), 256>>>(in, seg, stats, out, C, HW, logW,
                                                sh, px, 1.0f / (float)HW);
}

static inline void launch_up2(const float* in, float* out, int BC, int Hin, int Win) {
    int total = BC * 2 * Hin * Win;   // one thread per 2 output pixels
    up2_kernel<<<(total + 255) / 256, 256>>>(in, out, BC, Hin, Win,
                                             ilog2i(Win), ilog2i(2 * Hin));
}

extern "C" void kernel_launch(void* const* d_in, const int* in_sizes, int n_in,
                              void* d_out, int out_size) {
    const float* x   = (const float*)d_in[0];
    const int*   seg = (const int*)  d_in[1];
    const float* w1 = (const float*)d_in[2];   const float* b1 = (const float*)d_in[3];
    const float* w2 = (const float*)d_in[4];   const float* b2 = (const float*)d_in[5];
    const float* w3 = (const float*)d_in[6];   const float* b3 = (const float*)d_in[7];
    const float* w4 = (const float*)d_in[8];   const float* b4 = (const float*)d_in[9];
    const float* w5 = (const float*)d_in[10];  const float* b5 = (const float*)d_in[11];
    const float* w6 = (const float*)d_in[12];  const float* b6 = (const float*)d_in[13];
    const float* w7 = (const float*)d_in[14];  const float* b7 = (const float*)d_in[15];
    const float* w8 = (const float*)d_in[16];  const float* b8 = (const float*)d_in[17];
    const float* wf = (const float*)d_in[18];  const float* bf = (const float*)d_in[19];

    float *A, *Bb, *st;
    cudaGetSymbolAddress((void**)&A,  g_bufA);
    cudaGetSymbolAddress((void**)&Bb, g_bufB);
    cudaGetSymbolAddress((void**)&st, g_stats);

    // stage 1 @ 64x64
    launch_conv(x, w1, b1, A, 4, 512, 256, 64, 64, 1);
    launch_segnorm(A, seg, st, Bb, 4, 256, 64, 64);
    launch_up2(Bb, A, 4 * 256, 64, 64);            // -> 128x128

    // stage 2 @ 128x128
    launch_conv(A,  w2, b2, Bb, 4, 256, 256, 128, 128, 1);
    launch_conv(Bb, w3, b3, A,  4, 256, 256, 128, 128, 1);
    launch_conv(A,  w4, b4, Bb, 4, 256, 256, 128, 128, 1);
    launch_conv(Bb, w5, b5, A,  4, 256, 128, 128, 128, 1);
    launch_segnorm(A, seg, st, Bb, 4, 128, 128, 128);
    launch_up2(Bb, A, 4 * 128, 128, 128);          // -> 256x256

    // stage 3 @ 256x256
    launch_conv(A,  w6, b6, Bb, 4, 128, 128, 256, 256, 1);
    launch_conv(Bb, w7, b7, A,  4, 128, 64, 256, 256, 1);
    launch_segnorm(A, seg, st, Bb, 4, 64, 256, 256);
    launch_up2(Bb, A, 4 * 64, 256, 256);           // -> 512x512

    // stage 4 @ 512x512
    launch_conv(A,  w8, b8, Bb, 4, 64, 64, 512, 512, 1);
    launch_conv(Bb, wf, bf, (float*)d_out, 4, 64, 3, 512, 512, 0);  // no relu
}

// round 11
// speedup vs baseline: 2.8116x; 2.7197x over previous
#include <cuda_runtime.h>
#include <cuda_bf16.h>
#include <cstdint>

#define NUM_CLASSES 8
#define EPS_SN 1e-5f
#define CB  8
#define CCH 8
#define PY  4

// ---------------- scratch (device globals; no allocation allowed) ------------
__device__ float g_bufA[67108864];
__device__ float g_bufB[67108864];
__device__ __nv_bfloat16 g_Ph[67108864];   // NHWC bf16 hi
__device__ __nv_bfloat16 g_Pl[67108864];   // NHWC bf16 lo
__device__ __nv_bfloat16 g_Wh[1179648];    // [tap][coPad][ci] hi
__device__ __nv_bfloat16 g_Wl[1179648];
__device__ float g_stats[16384];

// ---------------- warp-MMA helpers (family-compatible: sm_80+) ----------------
__device__ __forceinline__ uint32_t smem_u32(const void* p) {
    uint32_t a;
    asm("{ .reg .u64 t; cvta.to.shared.u64 t, %1; cvt.u32.u64 %0, t; }" : "=r"(a) : "l"(p));
    return a;
}
__device__ __forceinline__ void ldsm4(uint32_t& r0, uint32_t& r1, uint32_t& r2,
                                      uint32_t& r3, uint32_t a) {
    asm volatile("ldmatrix.sync.aligned.m8n8.x4.shared.b16 {%0,%1,%2,%3}, [%4];"
                 : "=r"(r0), "=r"(r1), "=r"(r2), "=r"(r3) : "r"(a));
}
__device__ __forceinline__ void mma16816(float* c, uint32_t a0, uint32_t a1,
                                         uint32_t a2, uint32_t a3,
                                         uint32_t b0, uint32_t b1) {
    asm volatile("mma.sync.aligned.m16n8k16.row.col.f32.bf16.bf16.f32 "
                 "{%0,%1,%2,%3}, {%4,%5,%6,%7}, {%8,%9}, {%0,%1,%2,%3};"
                 : "+f"(c[0]), "+f"(c[1]), "+f"(c[2]), "+f"(c[3])
                 : "r"(a0), "r"(a1), "r"(a2), "r"(a3), "r"(b0), "r"(b1));
}

// ---------------- NCHW fp32 -> NHWC bf16 hi/lo split --------------------------
__global__ __launch_bounds__(256) void nchw_split_kernel(
    const float* __restrict__ in, __nv_bfloat16* __restrict__ ph,
    __nv_bfloat16* __restrict__ pl, int Cin, int H, int W, int cinBlocks)
{
    __shared__ float s[32][33];
    const int b   = blockIdx.z / cinBlocks;
    const int ci0 = (blockIdx.z % cinBlocks) << 5;
    const int y   = blockIdx.y;
    const int x0  = blockIdx.x << 5;
    const size_t chS = (size_t)H * W;
    const float* ip = in + ((size_t)(b * Cin + ci0) * H + y) * W + x0;
#pragma unroll
    for (int i = 0; i < 4; i++)
        s[threadIdx.y + 8 * i][threadIdx.x] = ip[(size_t)(threadIdx.y + 8 * i) * chS + threadIdx.x];
    __syncthreads();
    const size_t ob = ((size_t)b * H * W + (size_t)y * W + x0) * Cin + ci0;
#pragma unroll
    for (int i = 0; i < 4; i++) {
        int xl = threadIdx.y + 8 * i;
        float v = s[threadIdx.x][xl];
        __nv_bfloat16 h = __float2bfloat16(v);
        size_t a = ob + (size_t)xl * Cin + threadIdx.x;
        ph[a] = h;
        pl[a] = __float2bfloat16(v - __bfloat162float(h));
    }
}

// ---------------- weight prep: [co][ci][3][3] -> [tap][coPad][ci] hi/lo -------
__global__ __launch_bounds__(256) void prep_w_kernel(
    const float* __restrict__ w, __nv_bfloat16* __restrict__ wh,
    __nv_bfloat16* __restrict__ wl, int Cout, int Cpad, int Cin, int n)
{
    int i = blockIdx.x * 256 + threadIdx.x;
    if (i >= n) return;
    int tap = i / (Cpad * Cin);
    int rem = i - tap * Cpad * Cin;
    int co = rem / Cin, ci = rem - co * Cin;
    float v = (co < Cout) ? w[((size_t)co * Cin + ci) * 9 + tap] : 0.f;
    __nv_bfloat16 h = __float2bfloat16(v);
    wh[i] = h;
    wl[i] = __float2bfloat16(v - __bfloat162float(h));
}

// ---------------- warp-MMA implicit-GEMM 3x3 conv (bf16 split) ----------------
// Grid (HW/128, B, Cpad/128), block 256 (8 warps, 4m x 2n).
// Block tile M=128 co x N=128 pix; warp tile 32 x 64.
// smem: Ah | Al | Bh | Bl, each [128 rows][64 ci] bf16 = 16KB, XOR-swizzled.
#define CONV_DSMEM (4 * 16384 + 128)
__global__ __launch_bounds__(256) void conv_mma_kernel(
    const __nv_bfloat16* __restrict__ Ph, const __nv_bfloat16* __restrict__ Pl,
    const __nv_bfloat16* __restrict__ Wh, const __nv_bfloat16* __restrict__ Wl,
    const float* __restrict__ bias, float* __restrict__ out,
    int Cin, int Cout, int H, int W, int logW, int logC)
{
    extern __shared__ char smraw[];
    const uint32_t sb0 = smem_u32(smraw);
    const uint32_t sb = (sb0 + 127) & ~127u;
    char* sm = smraw + (sb - sb0);

    const int tid = threadIdx.x;
    const int wid = tid >> 5, lane = tid & 31;
    const int mbase = (wid & 3) << 5;     // 0,32,64,96
    const int nbase = (wid >> 2) << 6;    // 0,64

    const int p0  = blockIdx.x << 7;
    const int b   = blockIdx.y;
    const int co0 = blockIdx.z << 7;
    const int Cpad = gridDim.z << 7;
    const int HW = H * W;
    const __nv_bfloat16* PhB = Ph + (size_t)b * HW * Cin;
    const __nv_bfloat16* PlB = Pl + (size_t)b * HW * Cin;

    float acc[2][8][4];
#pragma unroll
    for (int mt = 0; mt < 2; mt++)
#pragma unroll
        for (int nt = 0; nt < 8; nt++)
#pragma unroll
            for (int e = 0; e < 4; e++) acc[mt][nt][e] = 0.f;

    const int R = 9 << logC;
    const int cMask = (1 << logC) - 1;

    // staging lane mapping: 8 lanes x 16B cover one 128B row
    const int c16 = tid & 7;
    const int rg  = tid >> 3;             // 0..31
    // ldmatrix lane constants
    const uint32_t xorv = (uint32_t)(lane & 7) << 4;
    const int matq = lane >> 3;           // 0..3
    const int rowA = ((matq & 1) << 3) + (lane & 7);
    const int kbA16 = (matq >> 1) << 4;   // 0 or 16 bytes
    const int rowB = ((matq >> 1) << 3) + (lane & 7);
    const int kbB16 = (matq & 1) << 4;

    for (int r = 0; r < R; r++) {
        const int tap = r >> logC, c = r & cMask;
        const int dy = tap / 3 - 1, dx = tap - (tap / 3) * 3 - 1;

        // ---- stage 64-ci chunk ----
#pragma unroll
        for (int k = 0; k < 4; k++) {
            int row = rg + (k << 5);
            uint32_t off = (uint32_t)(row << 7) + (((uint32_t)c16 << 4) ^ (((uint32_t)(row & 7)) << 4));
            size_t gA = ((size_t)tap * Cpad + co0 + row) * Cin + (c << 6) + (c16 << 3);
            *(float4*)(sm + off)         = *(const float4*)(Wh + gA);
            *(float4*)(sm + 16384 + off) = *(const float4*)(Wl + gA);
            int p = p0 + row;
            int y = p >> logW, x = p & (W - 1);
            int yy = y + dy; yy = (yy < 0) ? 1 : ((yy >= H) ? H - 2 : yy);
            int xx = x + dx; xx = (xx < 0) ? 1 : ((xx >= W) ? W - 2 : xx);
            size_t gB = (size_t)(yy * W + xx) * Cin + (c << 6) + (c16 << 3);
            *(float4*)(sm + 32768 + off) = *(const float4*)(PhB + gB);
            *(float4*)(sm + 49152 + off) = *(const float4*)(PlB + gB);
        }
        __syncthreads();

        // ---- compute: 4 k-steps of 16 ----
#pragma unroll
        for (int ks = 0; ks < 4; ks++) {
            const uint32_t kb = (uint32_t)(ks << 5);
            uint32_t ah[2][4], al[2][4];
#pragma unroll
            for (int mt = 0; mt < 2; mt++) {
                int rowm = mbase + (mt << 4) + rowA;
                uint32_t ad = sb + (uint32_t)(rowm << 7) + ((kb + kbA16) ^ xorv);
                ldsm4(ah[mt][0], ah[mt][1], ah[mt][2], ah[mt][3], ad);
                ldsm4(al[mt][0], al[mt][1], al[mt][2], al[mt][3], ad + 16384);
            }
#pragma unroll
            for (int ntp = 0; ntp < 4; ntp++) {
                int rown = nbase + (ntp << 4) + rowB;
                uint32_t bd = sb + 32768 + (uint32_t)(rown << 7) + ((kb + kbB16) ^ xorv);
                uint32_t bh[4], bl[4];
                ldsm4(bh[0], bh[1], bh[2], bh[3], bd);
                ldsm4(bl[0], bl[1], bl[2], bl[3], bd + 16384);
#pragma unroll
                for (int mt = 0; mt < 2; mt++) {
                    float* c0 = acc[mt][ntp * 2];
                    float* c1 = acc[mt][ntp * 2 + 1];
                    mma16816(c0, ah[mt][0], ah[mt][1], ah[mt][2], ah[mt][3], bh[0], bh[1]);
                    mma16816(c0, ah[mt][0], ah[mt][1], ah[mt][2], ah[mt][3], bl[0], bl[1]);
                    mma16816(c0, al[mt][0], al[mt][1], al[mt][2], al[mt][3], bh[0], bh[1]);
                    mma16816(c1, ah[mt][0], ah[mt][1], ah[mt][2], ah[mt][3], bh[2], bh[3]);
                    mma16816(c1, ah[mt][0], ah[mt][1], ah[mt][2], ah[mt][3], bl[2], bl[3]);
                    mma16816(c1, al[mt][0], al[mt][1], al[mt][2], al[mt][3], bh[2], bh[3]);
                }
            }
        }
        __syncthreads();
    }

    // ---- epilogue: bias + relu, NCHW float2 stores ----
#pragma unroll
    for (int mt = 0; mt < 2; mt++) {
#pragma unroll
        for (int hh = 0; hh < 2; hh++) {
            int co = co0 + mbase + (mt << 4) + (lane >> 2) + (hh << 3);
            if (co < Cout) {
                float bv = bias[co];
                float* op = out + (size_t)(b * Cout + co) * HW + p0 + nbase + ((lane & 3) << 1);
#pragma unroll
                for (int nt = 0; nt < 8; nt++) {
                    float2 v;
                    v.x = fmaxf(acc[mt][nt][hh * 2]     + bv, 0.f);
                    v.y = fmaxf(acc[mt][nt][hh * 2 + 1] + bv, 0.f);
                    *(float2*)(op + (nt << 3)) = v;
                }
            }
        }
    }
}

// ---------------- fp32 direct conv (final 64->3 layer, no relu) ---------------
__global__ __launch_bounds__(256) void conv3x3_kernel(
    const float* __restrict__ in, const float* __restrict__ wgt,
    const float* __restrict__ bias, float* __restrict__ out,
    int Cin, int Cout, int H, int W, int tilesY, int doRelu)
{
    __shared__ __align__(16) float s_in[CCH][34][34];
    __shared__ __align__(16) float s_w[CCH][9][CB];
    const int tx = threadIdx.x, ty = threadIdx.y;
    const int tid = ty * 32 + tx;
    const int tileY = blockIdx.y % tilesY;
    const int b = blockIdx.y / tilesY;
    const int co0 = blockIdx.z * CB;
    const int x0 = blockIdx.x * 32, y0 = tileY * 32;
    float acc[PY][CB];
#pragma unroll
    for (int p = 0; p < PY; p++)
#pragma unroll
        for (int j = 0; j < CB; j++) acc[p][j] = 0.f;
    const float* inB = in + (size_t)b * Cin * H * W;
    for (int cin0 = 0; cin0 < Cin; cin0 += CCH) {
        __syncthreads();
        for (int i = tid; i < CCH * 1156; i += 256) {
            int ci = i / 1156, rem = i - ci * 1156;
            int r = rem / 34, c = rem - r * 34;
            int gr = y0 - 1 + r, gc = x0 - 1 + c;
            gr = (gr < 0) ? -gr : ((gr >= H) ? 2 * H - 2 - gr : gr);
            gc = (gc < 0) ? -gc : ((gc >= W) ? 2 * W - 2 - gc : gc);
            s_in[ci][r][c] = inB[(size_t)(cin0 + ci) * H * W + gr * W + gc];
        }
        for (int i = tid; i < CCH * 9 * CB; i += 256) {
            int ci = i / (9 * CB), rem = i - ci * (9 * CB);
            int k = rem / CB, j = rem - k * CB;
            int co = co0 + j;
            s_w[ci][k][j] = (co < Cout) ? wgt[((size_t)co * Cin + cin0 + ci) * 9 + k] : 0.f;
        }
        __syncthreads();
#pragma unroll 1
        for (int ci = 0; ci < CCH; ci++) {
            float dp[6][3];
#pragma unroll
            for (int rr = 0; rr < 6; rr++)
#pragma unroll
                for (int c = 0; c < 3; c++) dp[rr][c] = s_in[ci][ty * PY + rr][tx + c];
#pragma unroll
            for (int kr = 0; kr < 3; kr++)
#pragma unroll
                for (int kc = 0; kc < 3; kc++) {
#pragma unroll
                    for (int p = 0; p < PY; p++) {
                        float d = dp[kr + p][kc];
#pragma unroll
                        for (int j = 0; j < CB; j++)
                            acc[p][j] = fmaf(d, s_w[ci][kr * 3 + kc][j], acc[p][j]);
                    }
                }
        }
    }
    const int x = x0 + tx, yBase = y0 + ty * PY;
#pragma unroll
    for (int p = 0; p < PY; p++) {
        int y = yBase + p;
#pragma unroll
        for (int j = 0; j < CB; j++) {
            int co = co0 + j;
            if (co < Cout) {
                float r = acc[p][j] + bias[co];
                if (doRelu) r = fmaxf(r, 0.f);
                out[((size_t)(b * Cout + co) * H + y) * W + x] = r;
            }
        }
    }
}

// ---------------- per-class instance-norm ------------------------------------
__global__ __launch_bounds__(256) void segnorm_stats(
    const float* __restrict__ x, const int* __restrict__ seg,
    float* __restrict__ stats, int C, int HW, int logW, int sh)
{
    const int bc = blockIdx.x, b = bc / C;
    const float* xp = x + (size_t)bc * HW;
    const int* sp = seg + b * 4096;
    const int Wm1 = (1 << logW) - 1;
    float s[8] = {0}, q[8] = {0};
    for (int i = threadIdx.x; i < HW; i += 256) {
        int h = i >> logW, wd = i & Wm1;
        int cls = sp[((h >> sh) << 6) + (wd >> sh)];
        float v = xp[i], v2 = v * v;
#pragma unroll
        for (int k = 0; k < 8; k++)
            if (cls == k) { s[k] += v; q[k] += v2; }
    }
#pragma unroll
    for (int k = 0; k < 8; k++)
#pragma unroll
        for (int o = 16; o > 0; o >>= 1) {
            s[k] += __shfl_xor_sync(0xffffffffu, s[k], o);
            q[k] += __shfl_xor_sync(0xffffffffu, q[k], o);
        }
    __shared__ float shs[8][8], shq[8][8];
    int warp = threadIdx.x >> 5, lane = threadIdx.x & 31;
    if (lane == 0)
#pragma unroll
        for (int k = 0; k < 8; k++) { shs[warp][k] = s[k]; shq[warp][k] = q[k]; }
    __syncthreads();
    if (threadIdx.x < 8) {
        float S = 0, Q = 0;
#pragma unroll
        for (int w = 0; w < 8; w++) { S += shs[w][threadIdx.x]; Q += shq[w][threadIdx.x]; }
        stats[bc * 16 + threadIdx.x * 2] = S;
        stats[bc * 16 + threadIdx.x * 2 + 1] = Q;
    }
}

__global__ __launch_bounds__(256) void segnorm_apply(
    const float* __restrict__ x, const int* __restrict__ seg,
    const float* __restrict__ stats, float* __restrict__ out,
    int C, int HW, int logW, int sh, int pxPerChunk, float invHW)
{
    const int bc = blockIdx.x, b = bc / C;
    __shared__ float s_rs[8], s_muR[8];
    if (threadIdx.x < 8) {
        float S = stats[bc * 16 + threadIdx.x * 2];
        float Q = stats[bc * 16 + threadIdx.x * 2 + 1];
        float mu = S * invHW;
        float var = Q * invHW - mu * mu;
        float r = rsqrtf(var + EPS_SN);
        s_rs[threadIdx.x] = r;
        s_muR[threadIdx.x] = mu * r;
    }
    __syncthreads();
    float K = 0.f;
#pragma unroll
    for (int k = 0; k < 8; k++) K += s_muR[k];
    const float* xp = x + (size_t)bc * HW;
    float* op = out + (size_t)bc * HW;
    const int* sp = seg + b * 4096;
    const int Wm1 = (1 << logW) - 1;
    const int end = min(HW, (int)((blockIdx.y + 1) * pxPerChunk));
    for (int i = blockIdx.y * pxPerChunk + threadIdx.x; i < end; i += 256) {
        int h = i >> logW, wd = i & Wm1;
        int cls = sp[((h >> sh) << 6) + (wd >> sh)];
        op[i] = xp[i] * s_rs[cls] - K;
    }
}

// ---------------- bilinear 2x upsample ---------------------------------------
__global__ __launch_bounds__(256) void up2_kernel(
    const float* __restrict__ in, float* __restrict__ out,
    int BC, int Hin, int Win, int logWin, int logHo)
{
    const int Ho = Hin * 2, Wo = Win * 2;
    const int total = BC << (logWin + logHo);
    int i = blockIdx.x * 256 + threadIdx.x;
    if (i >= total) return;
    int ix = i & (Win - 1);
    int t = i >> logWin;
    int yo = t & (Ho - 1);
    int bc = t >> logHo;
    int iy = yo >> 1;
    int y0, y1;
    float wy0, wy1;
    if (yo & 1) { y0 = iy; y1 = min(iy + 1, Hin - 1); wy0 = 0.75f; wy1 = 0.25f; }
    else        { y0 = max(iy - 1, 0); y1 = iy;       wy0 = 0.25f; wy1 = 0.75f; }
    int xm = max(ix - 1, 0), xp = min(ix + 1, Win - 1);
    const float* p = in + (size_t)bc * Hin * Win;
    const float* r0 = p + y0 * Win;
    const float* r1 = p + y1 * Win;
    float am = r0[xm], a0 = r0[ix], ap = r0[xp];
    float bm = r1[xm], b0 = r1[ix], bp = r1[xp];
    float2 v;
    v.x = wy0 * (0.25f * am + 0.75f * a0) + wy1 * (0.25f * bm + 0.75f * b0);
    v.y = wy0 * (0.75f * a0 + 0.25f * ap) + wy1 * (0.75f * b0 + 0.25f * bp);
    *(float2*)(out + ((size_t)bc * Ho + yo) * Wo + 2 * ix) = v;
}

// ---------------- host orchestration -----------------------------------------
static inline int ilog2i(int v) { int l = 0; while ((1 << l) < v) l++; return l; }

struct Bufs { __nv_bfloat16 *ph, *pl, *wh, *wl; };

static void run_conv_mma(const float* in, const float* w, const float* bias,
                         float* out, const Bufs& bf, int B, int Cin, int Cout,
                         int H, int W) {
    nchw_split_kernel<<<dim3(W / 32, H, B * (Cin / 32)), dim3(32, 8)>>>(
        in, bf.ph, bf.pl, Cin, H, W, Cin / 32);
    int Cpad = ((Cout + 127) / 128) * 128;
    int n = 9 * Cpad * Cin;
    prep_w_kernel<<<(n + 255) / 256, 256>>>(w, bf.wh, bf.wl, Cout, Cpad, Cin, n);
    conv_mma_kernel<<<dim3((H * W) / 128, B, Cpad / 128), 256, CONV_DSMEM>>>(
        bf.ph, bf.pl, bf.wh, bf.wl, bias, out, Cin, Cout, H, W,
        ilog2i(W), ilog2i(Cin / 64));
}

static void launch_segnorm(const float* in, const int* seg, float* stats,
                           float* out, int B, int C, int H, int W) {
    int HW = H * W, logW = ilog2i(W), sh = ilog2i(H / 64);
    segnorm_stats<<<B * C, 256>>>(in, seg, stats, C, HW, logW, sh);
    int chunks = (HW > 16384) ? (HW >> 14) : 1;
    segnorm_apply<<<dim3(B * C, chunks), 256>>>(in, seg, stats, out, C, HW, logW,
                                                sh, HW / chunks, 1.0f / (float)HW);
}

static void launch_up2(const float* in, float* out, int BC, int Hin, int Win) {
    int total = BC * 2 * Hin * Win;
    up2_kernel<<<(total + 255) / 256, 256>>>(in, out, BC, Hin, Win,
                                             ilog2i(Win), ilog2i(2 * Hin));
}

extern "C" void kernel_launch(void* const* d_in, const int* in_sizes, int n_in,
                              void* d_out, int out_size) {
    const float* x   = (const float*)d_in[0];
    const int*   seg = (const int*)  d_in[1];
    const float *w1 = (const float*)d_in[2],  *b1 = (const float*)d_in[3];
    const float *w2 = (const float*)d_in[4],  *b2 = (const float*)d_in[5];
    const float *w3 = (const float*)d_in[6],  *b3 = (const float*)d_in[7];
    const float *w4 = (const float*)d_in[8],  *b4 = (const float*)d_in[9];
    const float *w5 = (const float*)d_in[10], *b5 = (const float*)d_in[11];
    const float *w6 = (const float*)d_in[12], *b6 = (const float*)d_in[13];
    const float *w7 = (const float*)d_in[14], *b7 = (const float*)d_in[15];
    const float *w8 = (const float*)d_in[16], *b8 = (const float*)d_in[17];
    const float *wf = (const float*)d_in[18], *bf_ = (const float*)d_in[19];

    cudaFuncSetAttribute(conv_mma_kernel,
                         cudaFuncAttributeMaxDynamicSharedMemorySize, CONV_DSMEM);

    float *A, *Bb, *st;
    Bufs bf;
    cudaGetSymbolAddress((void**)&A,  g_bufA);
    cudaGetSymbolAddress((void**)&Bb, g_bufB);
    cudaGetSymbolAddress((void**)&st, g_stats);
    cudaGetSymbolAddress((void**)&bf.ph, g_Ph);
    cudaGetSymbolAddress((void**)&bf.pl, g_Pl);
    cudaGetSymbolAddress((void**)&bf.wh, g_Wh);
    cudaGetSymbolAddress((void**)&bf.wl, g_Wl);

    // stage 1 @ 64x64
    run_conv_mma(x, w1, b1, A, bf, 4, 512, 256, 64, 64);
    launch_segnorm(A, seg, st, Bb, 4, 256, 64, 64);
    launch_up2(Bb, A, 4 * 256, 64, 64);
    // stage 2 @ 128x128
    run_conv_mma(A,  w2, b2, Bb, bf, 4, 256, 256, 128, 128);
    run_conv_mma(Bb, w3, b3, A,  bf, 4, 256, 256, 128, 128);
    run_conv_mma(A,  w4, b4, Bb, bf, 4, 256, 256, 128, 128);
    run_conv_mma(Bb, w5, b5, A,  bf, 4, 256, 128, 128, 128);
    launch_segnorm(A, seg, st, Bb, 4, 128, 128, 128);
    launch_up2(Bb, A, 4 * 128, 128, 128);
    // stage 3 @ 256x256
    run_conv_mma(A,  w6, b6, Bb, bf, 4, 128, 128, 256, 256);
    run_conv_mma(Bb, w7, b7, A,  bf, 4, 128, 64, 256, 256);
    launch_segnorm(A, seg, st, Bb, 4, 64, 256, 256);
    launch_up2(Bb, A, 4 * 64, 256, 256);
    // stage 4 @ 512x512
    run_conv_mma(A, w8, b8, Bb, bf, 4, 64, 64, 512, 512);
    conv3x3_kernel<<<dim3(512 / 32, (512 / 32) * 4, 1), dim3(32, 8)>>>(
        Bb, wf, bf_, (float*)d_out, 64, 3, 512, 512, 512 / 32, 0);
}

// round 12
// speedup vs baseline: 4.0694x; 1.4474x over previous
#include <cuda_runtime.h>
#include <cuda_bf16.h>
#include <cstdint>

#define NUM_CLASSES 8
#define EPS_SN 1e-5f
#define CCH 8
#define PY  4

// ---------------- scratch (device globals; no allocation allowed) ------------
__device__ float g_bufA[67108864];
__device__ float g_bufB[67108864];
__device__ __nv_bfloat16 g_Ph[67108864];   // NHWC bf16 hi
__device__ __nv_bfloat16 g_Pl[67108864];   // NHWC bf16 lo
__device__ __nv_bfloat16 g_Wh[1179648];    // [tap][coPad][ci] hi
__device__ __nv_bfloat16 g_Wl[1179648];
__device__ float g_stats[16384];

// ---------------- warp-MMA helpers (family-compatible: sm_80+) ----------------
__device__ __forceinline__ uint32_t smem_u32(const void* p) {
    uint32_t a;
    asm("{ .reg .u64 t; cvta.to.shared.u64 t, %1; cvt.u32.u64 %0, t; }" : "=r"(a) : "l"(p));
    return a;
}
__device__ __forceinline__ void ldsm4(uint32_t& r0, uint32_t& r1, uint32_t& r2,
                                      uint32_t& r3, uint32_t a) {
    asm volatile("ldmatrix.sync.aligned.m8n8.x4.shared.b16 {%0,%1,%2,%3}, [%4];"
                 : "=r"(r0), "=r"(r1), "=r"(r2), "=r"(r3) : "r"(a));
}
__device__ __forceinline__ void mma16816(float* c, uint32_t a0, uint32_t a1,
                                         uint32_t a2, uint32_t a3,
                                         uint32_t b0, uint32_t b1) {
    asm volatile("mma.sync.aligned.m16n8k16.row.col.f32.bf16.bf16.f32 "
                 "{%0,%1,%2,%3}, {%4,%5,%6,%7}, {%8,%9}, {%0,%1,%2,%3};"
                 : "+f"(c[0]), "+f"(c[1]), "+f"(c[2]), "+f"(c[3])
                 : "r"(a0), "r"(a1), "r"(a2), "r"(a3), "r"(b0), "r"(b1));
}
__device__ __forceinline__ void cpasync16(uint32_t dst, const void* src) {
    asm volatile("cp.async.cg.shared.global [%0], [%1], 16;" :: "r"(dst), "l"(src));
}
#define CP_COMMIT() asm volatile("cp.async.commit_group;" ::: "memory")
#define CP_WAIT1()  asm volatile("cp.async.wait_group 1;" ::: "memory")
#define CP_WAIT0()  asm volatile("cp.async.wait_group 0;" ::: "memory")

// ---------------- NCHW fp32 -> NHWC bf16 hi/lo split --------------------------
__global__ __launch_bounds__(256) void nchw_split_kernel(
    const float* __restrict__ in, __nv_bfloat16* __restrict__ ph,
    __nv_bfloat16* __restrict__ pl, int Cin, int H, int W, int cinBlocks)
{
    __shared__ float s[32][33];
    const int b   = blockIdx.z / cinBlocks;
    const int ci0 = (blockIdx.z % cinBlocks) << 5;
    const int y   = blockIdx.y;
    const int x0  = blockIdx.x << 5;
    const size_t chS = (size_t)H * W;
    const float* ip = in + ((size_t)(b * Cin + ci0) * H + y) * W + x0;
#pragma unroll
    for (int i = 0; i < 4; i++)
        s[threadIdx.y + 8 * i][threadIdx.x] = ip[(size_t)(threadIdx.y + 8 * i) * chS + threadIdx.x];
    __syncthreads();
    const size_t ob = ((size_t)b * H * W + (size_t)y * W + x0) * Cin + ci0;
#pragma unroll
    for (int i = 0; i < 4; i++) {
        int xl = threadIdx.y + 8 * i;
        float v = s[threadIdx.x][xl];
        __nv_bfloat16 h = __float2bfloat16(v);
        size_t a = ob + (size_t)xl * Cin + threadIdx.x;
        ph[a] = h;
        pl[a] = __float2bfloat16(v - __bfloat162float(h));
    }
}

// ---------------- weight prep: [co][ci][3][3] -> [tap][coPad][ci] hi/lo -------
__global__ __launch_bounds__(256) void prep_w_kernel(
    const float* __restrict__ w, __nv_bfloat16* __restrict__ wh,
    __nv_bfloat16* __restrict__ wl, int Cout, int Cpad, int Cin, int n)
{
    int i = blockIdx.x * 256 + threadIdx.x;
    if (i >= n) return;
    int tap = i / (Cpad * Cin);
    int rem = i - tap * Cpad * Cin;
    int co = rem / Cin, ci = rem - co * Cin;
    float v = (co < Cout) ? w[((size_t)co * Cin + ci) * 9 + tap] : 0.f;
    __nv_bfloat16 h = __float2bfloat16(v);
    wh[i] = h;
    wl[i] = __float2bfloat16(v - __bfloat162float(h));
}

// ---------------- warp-MMA implicit-GEMM 3x3 conv (bf16 split) ----------------
// Template MT = M tile (128: warps 4m x 2n, warp 32x64; 64: warps 2m x 4n, 32x32).
// N tile = 128 pixels. K staged in 64-ci chunks, cp.async double-buffered.
// Stage layout: Ah | Al | Bh | Bl (A planes MT*128B, B planes 16KB), XOR-swizzled.
template<int MT>
__global__ __launch_bounds__(256) void conv_mma_kernel(
    const __nv_bfloat16* __restrict__ Ph, const __nv_bfloat16* __restrict__ Pl,
    const __nv_bfloat16* __restrict__ Wh, const __nv_bfloat16* __restrict__ Wl,
    const float* __restrict__ bias, float* __restrict__ out,
    int Cin, int Cout, int H, int W, int logW, int logC)
{
    constexpr int ASZ = MT * 128;            // bytes per A plane
    constexpr int STG = 2 * ASZ + 32768;     // bytes per stage
    constexpr int NT  = (MT == 128) ? 8 : 4; // acc n-groups of 8 px per warp

    extern __shared__ char smraw[];
    const uint32_t sb0 = smem_u32(smraw);
    const uint32_t sb = (sb0 + 127) & ~127u;

    const int tid = threadIdx.x;
    const int wid = tid >> 5, lane = tid & 31;
    const int mbase = (MT == 128) ? ((wid & 3) << 5) : ((wid & 1) << 5);
    const int nbase = (MT == 128) ? ((wid >> 2) << 6) : ((wid >> 1) << 5);

    const int p0  = blockIdx.x << 7;
    const int b   = blockIdx.y;
    const int co0 = blockIdx.z * MT;
    const int Cpad = gridDim.z * MT;
    const int HW = H * W;
    const __nv_bfloat16* PhB = Ph + (size_t)b * HW * Cin;
    const __nv_bfloat16* PlB = Pl + (size_t)b * HW * Cin;

    float acc[2][NT][4];
#pragma unroll
    for (int mt = 0; mt < 2; mt++)
#pragma unroll
        for (int nt = 0; nt < NT; nt++)
#pragma unroll
            for (int e = 0; e < 4; e++) acc[mt][nt][e] = 0.f;

    const int R = 9 << logC;
    const int cMask = (1 << logC) - 1;

    // staging lane mapping: 8 lanes x 16B cover one 128B row
    const int c16 = tid & 7;
    const int rg  = tid >> 3;             // 0..31
    // ldmatrix lane constants
    const uint32_t xorv = (uint32_t)(lane & 7) << 4;
    const int matq = lane >> 3;
    const int rowA = ((matq & 1) << 3) + (lane & 7);
    const int kbA16 = (matq >> 1) << 4;
    const int rowB = ((matq >> 1) << 3) + (lane & 7);
    const int kbB16 = (matq & 1) << 4;

    auto stage = [&](int rr) {
        const uint32_t sbStg = sb + (uint32_t)(rr & 1) * STG;
        const int tap = rr >> logC, c = rr & cMask;
        const int dy = tap / 3 - 1, dx = tap - (tap / 3) * 3 - 1;
#pragma unroll
        for (int k = 0; k < MT / 32; k++) {
            int row = rg + (k << 5);
            uint32_t off = (uint32_t)(row << 7) + (((uint32_t)c16 << 4) ^ (((uint32_t)(row & 7)) << 4));
            size_t gA = ((size_t)tap * Cpad + co0 + row) * Cin + (c << 6) + (c16 << 3);
            cpasync16(sbStg + off,        Wh + gA);
            cpasync16(sbStg + ASZ + off,  Wl + gA);
        }
#pragma unroll
        for (int k = 0; k < 4; k++) {
            int row = rg + (k << 5);
            int p = p0 + row;
            int y = p >> logW, x = p & (W - 1);
            int yy = y + dy; yy = (yy < 0) ? 1 : ((yy >= H) ? H - 2 : yy);
            int xx = x + dx; xx = (xx < 0) ? 1 : ((xx >= W) ? W - 2 : xx);
            size_t gB = (size_t)(yy * W + xx) * Cin + (c << 6) + (c16 << 3);
            uint32_t off = (uint32_t)(row << 7) + (((uint32_t)c16 << 4) ^ (((uint32_t)(row & 7)) << 4));
            cpasync16(sbStg + 2 * ASZ + off,         PhB + gB);
            cpasync16(sbStg + 2 * ASZ + 16384 + off, PlB + gB);
        }
    };

    stage(0);
    CP_COMMIT();

    for (int r = 0; r < R; r++) {
        if (r + 1 < R) { stage(r + 1); CP_COMMIT(); CP_WAIT1(); }
        else          { CP_WAIT0(); }
        __syncthreads();

        const uint32_t base = sb + (uint32_t)(r & 1) * STG;
#pragma unroll
        for (int ks = 0; ks < 4; ks++) {
            const uint32_t kb = (uint32_t)(ks << 5);
            uint32_t ah[2][4], al[2][4];
#pragma unroll
            for (int mt = 0; mt < 2; mt++) {
                int rowm = mbase + (mt << 4) + rowA;
                uint32_t ad = base + (uint32_t)(rowm << 7) + ((kb + kbA16) ^ xorv);
                ldsm4(ah[mt][0], ah[mt][1], ah[mt][2], ah[mt][3], ad);
                ldsm4(al[mt][0], al[mt][1], al[mt][2], al[mt][3], ad + ASZ);
            }
#pragma unroll
            for (int ntp = 0; ntp < NT / 2; ntp++) {
                int rown = nbase + (ntp << 4) + rowB;
                uint32_t bd = base + 2 * ASZ + (uint32_t)(rown << 7) + ((kb + kbB16) ^ xorv);
                uint32_t bh[4], bl[4];
                ldsm4(bh[0], bh[1], bh[2], bh[3], bd);
                ldsm4(bl[0], bl[1], bl[2], bl[3], bd + 16384);
#pragma unroll
                for (int mt = 0; mt < 2; mt++) {
                    float* c0 = acc[mt][ntp * 2];
                    float* c1 = acc[mt][ntp * 2 + 1];
                    mma16816(c0, ah[mt][0], ah[mt][1], ah[mt][2], ah[mt][3], bh[0], bh[1]);
                    mma16816(c0, ah[mt][0], ah[mt][1], ah[mt][2], ah[mt][3], bl[0], bl[1]);
                    mma16816(c0, al[mt][0], al[mt][1], al[mt][2], al[mt][3], bh[0], bh[1]);
                    mma16816(c1, ah[mt][0], ah[mt][1], ah[mt][2], ah[mt][3], bh[2], bh[3]);
                    mma16816(c1, ah[mt][0], ah[mt][1], ah[mt][2], ah[mt][3], bl[2], bl[3]);
                    mma16816(c1, al[mt][0], al[mt][1], al[mt][2], al[mt][3], bh[2], bh[3]);
                }
            }
        }
        __syncthreads();
    }

    // ---- epilogue: bias + relu, NCHW float2 stores ----
#pragma unroll
    for (int mt = 0; mt < 2; mt++) {
#pragma unroll
        for (int hh = 0; hh < 2; hh++) {
            int co = co0 + mbase + (mt << 4) + (lane >> 2) + (hh << 3);
            if (co < Cout) {
                float bv = bias[co];
                float* op = out + (size_t)(b * Cout + co) * HW + p0 + nbase + ((lane & 3) << 1);
#pragma unroll
                for (int nt = 0; nt < NT; nt++) {
                    float2 v;
                    v.x = fmaxf(acc[mt][nt][hh * 2]     + bv, 0.f);
                    v.y = fmaxf(acc[mt][nt][hh * 2 + 1] + bv, 0.f);
                    *(float2*)(op + (nt << 3)) = v;
                }
            }
        }
    }
}

// ---------------- fp32 direct conv (final layer), CB templated ---------------
template<int CBT>
__global__ __launch_bounds__(256) void conv3x3_kernel(
    const float* __restrict__ in, const float* __restrict__ wgt,
    const float* __restrict__ bias, float* __restrict__ out,
    int Cin, int Cout, int H, int W, int tilesY, int doRelu)
{
    __shared__ __align__(16) float s_in[CCH][34][34];
    __shared__ __align__(16) float s_w[CCH][9][CBT];
    const int tx = threadIdx.x, ty = threadIdx.y;
    const int tid = ty * 32 + tx;
    const int tileY = blockIdx.y % tilesY;
    const int b = blockIdx.y / tilesY;
    const int co0 = blockIdx.z * CBT;
    const int x0 = blockIdx.x * 32, y0 = tileY * 32;
    float acc[PY][CBT];
#pragma unroll
    for (int p = 0; p < PY; p++)
#pragma unroll
        for (int j = 0; j < CBT; j++) acc[p][j] = 0.f;
    const float* inB = in + (size_t)b * Cin * H * W;
    for (int cin0 = 0; cin0 < Cin; cin0 += CCH) {
        __syncthreads();
        for (int i = tid; i < CCH * 1156; i += 256) {
            int ci = i / 1156, rem = i - ci * 1156;
            int r = rem / 34, c = rem - r * 34;
            int gr = y0 - 1 + r, gc = x0 - 1 + c;
            gr = (gr < 0) ? -gr : ((gr >= H) ? 2 * H - 2 - gr : gr);
            gc = (gc < 0) ? -gc : ((gc >= W) ? 2 * W - 2 - gc : gc);
            s_in[ci][r][c] = inB[(size_t)(cin0 + ci) * H * W + gr * W + gc];
        }
        for (int i = tid; i < CCH * 9 * CBT; i += 256) {
            int ci = i / (9 * CBT), rem = i - ci * (9 * CBT);
            int k = rem / CBT, j = rem - k * CBT;
            int co = co0 + j;
            s_w[ci][k][j] = (co < Cout) ? wgt[((size_t)co * Cin + cin0 + ci) * 9 + k] : 0.f;
        }
        __syncthreads();
#pragma unroll 1
        for (int ci = 0; ci < CCH; ci++) {
            float dp[6][3];
#pragma unroll
            for (int rr = 0; rr < 6; rr++)
#pragma unroll
                for (int c = 0; c < 3; c++) dp[rr][c] = s_in[ci][ty * PY + rr][tx + c];
#pragma unroll
            for (int kr = 0; kr < 3; kr++)
#pragma unroll
                for (int kc = 0; kc < 3; kc++) {
#pragma unroll
                    for (int p = 0; p < PY; p++) {
                        float d = dp[kr + p][kc];
#pragma unroll
                        for (int j = 0; j < CBT; j++)
                            acc[p][j] = fmaf(d, s_w[ci][kr * 3 + kc][j], acc[p][j]);
                    }
                }
        }
    }
    const int x = x0 + tx, yBase = y0 + ty * PY;
#pragma unroll
    for (int p = 0; p < PY; p++) {
        int y = yBase + p;
#pragma unroll
        for (int j = 0; j < CBT; j++) {
            int co = co0 + j;
            if (co < Cout) {
                float r = acc[p][j] + bias[co];
                if (doRelu) r = fmaxf(r, 0.f);
                out[((size_t)(b * Cout + co) * H + y) * W + x] = r;
            }
        }
    }
}

// ---------------- per-class instance-norm ------------------------------------
__global__ __launch_bounds__(256) void segnorm_stats(
    const float* __restrict__ x, const int* __restrict__ seg,
    float* __restrict__ stats, int C, int HW, int logW, int sh)
{
    const int bc = blockIdx.x, b = bc / C;
    const float* xp = x + (size_t)bc * HW;
    const int* sp = seg + b * 4096;
    const int Wm1 = (1 << logW) - 1;
    float s[8] = {0}, q[8] = {0};
    for (int i = threadIdx.x; i < HW; i += 256) {
        int h = i >> logW, wd = i & Wm1;
        int cls = sp[((h >> sh) << 6) + (wd >> sh)];
        float v = xp[i], v2 = v * v;
#pragma unroll
        for (int k = 0; k < 8; k++)
            if (cls == k) { s[k] += v; q[k] += v2; }
    }
#pragma unroll
    for (int k = 0; k < 8; k++)
#pragma unroll
        for (int o = 16; o > 0; o >>= 1) {
            s[k] += __shfl_xor_sync(0xffffffffu, s[k], o);
            q[k] += __shfl_xor_sync(0xffffffffu, q[k], o);
        }
    __shared__ float shs[8][8], shq[8][8];
    int warp = threadIdx.x >> 5, lane = threadIdx.x & 31;
    if (lane == 0)
#pragma unroll
        for (int k = 0; k < 8; k++) { shs[warp][k] = s[k]; shq[warp][k] = q[k]; }
    __syncthreads();
    if (threadIdx.x < 8) {
        float S = 0, Q = 0;
#pragma unroll
        for (int w = 0; w < 8; w++) { S += shs[w][threadIdx.x]; Q += shq[w][threadIdx.x]; }
        stats[bc * 16 + threadIdx.x * 2] = S;
        stats[bc * 16 + threadIdx.x * 2 + 1] = Q;
    }
}

__global__ __launch_bounds__(256) void segnorm_apply(
    const float* __restrict__ x, const int* __restrict__ seg,
    const float* __restrict__ stats, float* __restrict__ out,
    int C, int HW, int logW, int sh, int pxPerChunk, float invHW)
{
    const int bc = blockIdx.x, b = bc / C;
    __shared__ float s_rs[8], s_muR[8];
    if (threadIdx.x < 8) {
        float S = stats[bc * 16 + threadIdx.x * 2];
        float Q = stats[bc * 16 + threadIdx.x * 2 + 1];
        float mu = S * invHW;
        float var = Q * invHW - mu * mu;
        float r = rsqrtf(var + EPS_SN);
        s_rs[threadIdx.x] = r;
        s_muR[threadIdx.x] = mu * r;
    }
    __syncthreads();
    float K = 0.f;
#pragma unroll
    for (int k = 0; k < 8; k++) K += s_muR[k];
    const float* xp = x + (size_t)bc * HW;
    float* op = out + (size_t)bc * HW;
    const int* sp = seg + b * 4096;
    const int Wm1 = (1 << logW) - 1;
    const int end = min(HW, (int)((blockIdx.y + 1) * pxPerChunk));
    for (int i = blockIdx.y * pxPerChunk + threadIdx.x; i < end; i += 256) {
        int h = i >> logW, wd = i & Wm1;
        int cls = sp[((h >> sh) << 6) + (wd >> sh)];
        op[i] = xp[i] * s_rs[cls] - K;
    }
}

// ---------------- bilinear 2x upsample ---------------------------------------
__global__ __launch_bounds__(256) void up2_kernel(
    const float* __restrict__ in, float* __restrict__ out,
    int BC, int Hin, int Win, int logWin, int logHo)
{
    const int Ho = Hin * 2, Wo = Win * 2;
    const int total = BC << (logWin + logHo);
    int i = blockIdx.x * 256 + threadIdx.x;
    if (i >= total) return;
    int ix = i & (Win - 1);
    int t = i >> logWin;
    int yo = t & (Ho - 1);
    int bc = t >> logHo;
    int iy = yo >> 1;
    int y0, y1;
    float wy0, wy1;
    if (yo & 1) { y0 = iy; y1 = min(iy + 1, Hin - 1); wy0 = 0.75f; wy1 = 0.25f; }
    else        { y0 = max(iy - 1, 0); y1 = iy;       wy0 = 0.25f; wy1 = 0.75f; }
    int xm = max(ix - 1, 0), xp = min(ix + 1, Win - 1);
    const float* p = in + (size_t)bc * Hin * Win;
    const float* r0 = p + y0 * Win;
    const float* r1 = p + y1 * Win;
    float am = r0[xm], a0 = r0[ix], ap = r0[xp];
    float bm = r1[xm], b0 = r1[ix], bp = r1[xp];
    float2 v;
    v.x = wy0 * (0.25f * am + 0.75f * a0) + wy1 * (0.25f * bm + 0.75f * b0);
    v.y = wy0 * (0.75f * a0 + 0.25f * ap) + wy1 * (0.75f * b0 + 0.25f * bp);
    *(float2*)(out + ((size_t)bc * Ho + yo) * Wo + 2 * ix) = v;
}

// ---------------- host orchestration -----------------------------------------
static inline int ilog2i(int v) { int l = 0; while ((1 << l) < v) l++; return l; }

struct Bufs { __nv_bfloat16 *ph, *pl, *wh, *wl; };

#define DSMEM_128 (2 * (2 * 128 * 128 + 32768) + 128)
#define DSMEM_64  (2 * (2 * 64 * 128 + 32768) + 128)

static void run_conv_mma(const float* in, const float* w, const float* bias,
                         float* out, const Bufs& bf, int B, int Cin, int Cout,
                         int H, int W) {
    nchw_split_kernel<<<dim3(W / 32, H, B * (Cin / 32)), dim3(32, 8)>>>(
        in, bf.ph, bf.pl, Cin, H, W, Cin / 32);
    int MT = (Cout > 64) ? 128 : 64;
    int Cpad = ((Cout + MT - 1) / MT) * MT;
    int n = 9 * Cpad * Cin;
    prep_w_kernel<<<(n + 255) / 256, 256>>>(w, bf.wh, bf.wl, Cout, Cpad, Cin, n);
    if (MT == 128)
        conv_mma_kernel<128><<<dim3((H * W) / 128, B, Cpad / 128), 256, DSMEM_128>>>(
            bf.ph, bf.pl, bf.wh, bf.wl, bias, out, Cin, Cout, H, W,
            ilog2i(W), ilog2i(Cin / 64));
    else
        conv_mma_kernel<64><<<dim3((H * W) / 128, B, Cpad / 64), 256, DSMEM_64>>>(
            bf.ph, bf.pl, bf.wh, bf.wl, bias, out, Cin, Cout, H, W,
            ilog2i(W), ilog2i(Cin / 64));
}

static void launch_segnorm(const float* in, const int* seg, float* stats,
                           float* out, int B, int C, int H, int W) {
    int HW = H * W, logW = ilog2i(W), sh = ilog2i(H / 64);
    segnorm_stats<<<B * C, 256>>>(in, seg, stats, C, HW, logW, sh);
    int chunks = (HW > 16384) ? (HW >> 14) : 1;
    segnorm_apply<<<dim3(B * C, chunks), 256>>>(in, seg, stats, out, C, HW, logW,
                                                sh, HW / chunks, 1.0f / (float)HW);
}

static void launch_up2(const float* in, float* out, int BC, int Hin, int Win) {
    int total = BC * 2 * Hin * Win;
    up2_kernel<<<(total + 255) / 256, 256>>>(in, out, BC, Hin, Win,
                                             ilog2i(Win), ilog2i(2 * Hin));
}

extern "C" void kernel_launch(void* const* d_in, const int* in_sizes, int n_in,
                              void* d_out, int out_size) {
    const float* x   = (const float*)d_in[0];
    const int*   seg = (const int*)  d_in[1];
    const float *w1 = (const float*)d_in[2],  *b1 = (const float*)d_in[3];
    const float *w2 = (const float*)d_in[4],  *b2 = (const float*)d_in[5];
    const float *w3 = (const float*)d_in[6],  *b3 = (const float*)d_in[7];
    const float *w4 = (const float*)d_in[8],  *b4 = (const float*)d_in[9];
    const float *w5 = (const float*)d_in[10], *b5 = (const float*)d_in[11];
    const float *w6 = (const float*)d_in[12], *b6 = (const float*)d_in[13];
    const float *w7 = (const float*)d_in[14], *b7 = (const float*)d_in[15];
    const float *w8 = (const float*)d_in[16], *b8 = (const float*)d_in[17];
    const float *wf = (const float*)d_in[18], *bf_ = (const float*)d_in[19];

    cudaFuncSetAttribute(conv_mma_kernel<128>,
                         cudaFuncAttributeMaxDynamicSharedMemorySize, DSMEM_128);
    cudaFuncSetAttribute(conv_mma_kernel<64>,
                         cudaFuncAttributeMaxDynamicSharedMemorySize, DSMEM_64);

    float *A, *Bb, *st;
    Bufs bf;
    cudaGetSymbolAddress((void**)&A,  g_bufA);
    cudaGetSymbolAddress((void**)&Bb, g_bufB);
    cudaGetSymbolAddress((void**)&st, g_stats);
    cudaGetSymbolAddress((void**)&bf.ph, g_Ph);
    cudaGetSymbolAddress((void**)&bf.pl, g_Pl);
    cudaGetSymbolAddress((void**)&bf.wh, g_Wh);
    cudaGetSymbolAddress((void**)&bf.wl, g_Wl);

    // stage 1 @ 64x64
    run_conv_mma(x, w1, b1, A, bf, 4, 512, 256, 64, 64);
    launch_segnorm(A, seg, st, Bb, 4, 256, 64, 64);
    launch_up2(Bb, A, 4 * 256, 64, 64);
    // stage 2 @ 128x128
    run_conv_mma(A,  w2, b2, Bb, bf, 4, 256, 256, 128, 128);
    run_conv_mma(Bb, w3, b3, A,  bf, 4, 256, 256, 128, 128);
    run_conv_mma(A,  w4, b4, Bb, bf, 4, 256, 256, 128, 128);
    run_conv_mma(Bb, w5, b5, A,  bf, 4, 256, 128, 128, 128);
    launch_segnorm(A, seg, st, Bb, 4, 128, 128, 128);
    launch_up2(Bb, A, 4 * 128, 128, 128);
    // stage 3 @ 256x256
    run_conv_mma(A,  w6, b6, Bb, bf, 4, 128, 128, 256, 256);
    run_conv_mma(Bb, w7, b7, A,  bf, 4, 128, 64, 256, 256);
    launch_segnorm(A, seg, st, Bb, 4, 64, 256, 256);
    launch_up2(Bb, A, 4 * 64, 256, 256);
    // stage 4 @ 512x512
    run_conv_mma(A, w8, b8, Bb, bf, 4, 64, 64, 512, 512);
    conv3x3_kernel<4><<<dim3(512 / 32, (512 / 32) * 4, 1), dim3(32, 8)>>>(
        Bb, wf, bf_, (float*)d_out, 64, 3, 512, 512, 512 / 32, 0);
}

// round 13
// speedup vs baseline: 4.1532x; 1.0206x over previous
#include <cuda_runtime.h>
#include <cuda_bf16.h>
#include <cstdint>

#define NUM_CLASSES 8
#define EPS_SN 1e-5f
#define CCH 8
#define PY  4

// ---------------- scratch (device globals; no allocation allowed) ------------
__device__ float g_bufA[67108864];
__device__ float g_bufB[67108864];
__device__ __nv_bfloat16 g_P0h[67108864], g_P0l[67108864];  // NHWC ping
__device__ __nv_bfloat16 g_P1h[67108864], g_P1l[67108864];  // NHWC pong
__device__ __nv_bfloat16 g_Wh[1179648], g_Wl[1179648];      // [tap][coPad][ci]
__device__ float g_stats[16384];

// ---------------- warp-MMA helpers (family-compatible: sm_80+) ----------------
__device__ __forceinline__ uint32_t smem_u32(const void* p) {
    uint32_t a;
    asm("{ .reg .u64 t; cvta.to.shared.u64 t, %1; cvt.u32.u64 %0, t; }" : "=r"(a) : "l"(p));
    return a;
}
__device__ __forceinline__ void ldsm4(uint32_t& r0, uint32_t& r1, uint32_t& r2,
                                      uint32_t& r3, uint32_t a) {
    asm volatile("ldmatrix.sync.aligned.m8n8.x4.shared.b16 {%0,%1,%2,%3}, [%4];"
                 : "=r"(r0), "=r"(r1), "=r"(r2), "=r"(r3) : "r"(a));
}
__device__ __forceinline__ void mma16816(float* c, uint32_t a0, uint32_t a1,
                                         uint32_t a2, uint32_t a3,
                                         uint32_t b0, uint32_t b1) {
    asm volatile("mma.sync.aligned.m16n8k16.row.col.f32.bf16.bf16.f32 "
                 "{%0,%1,%2,%3}, {%4,%5,%6,%7}, {%8,%9}, {%0,%1,%2,%3};"
                 : "+f"(c[0]), "+f"(c[1]), "+f"(c[2]), "+f"(c[3])
                 : "r"(a0), "r"(a1), "r"(a2), "r"(a3), "r"(b0), "r"(b1));
}
__device__ __forceinline__ void cpasync16(uint32_t dst, const void* src) {
    asm volatile("cp.async.cg.shared.global [%0], [%1], 16;" :: "r"(dst), "l"(src));
}
#define CP_COMMIT() asm volatile("cp.async.commit_group;" ::: "memory")
#define CP_WAIT1()  asm volatile("cp.async.wait_group 1;" ::: "memory")
#define CP_WAIT0()  asm volatile("cp.async.wait_group 0;" ::: "memory")

// ---------------- NCHW fp32 -> NHWC bf16 hi/lo split (input x only) -----------
__global__ __launch_bounds__(256) void nchw_split_kernel(
    const float* __restrict__ in, __nv_bfloat16* __restrict__ ph,
    __nv_bfloat16* __restrict__ pl, int Cin, int H, int W, int cinBlocks)
{
    __shared__ float s[32][33];
    const int b   = blockIdx.z / cinBlocks;
    const int ci0 = (blockIdx.z % cinBlocks) << 5;
    const int y   = blockIdx.y;
    const int x0  = blockIdx.x << 5;
    const size_t chS = (size_t)H * W;
    const float* ip = in + ((size_t)(b * Cin + ci0) * H + y) * W + x0;
#pragma unroll
    for (int i = 0; i < 4; i++)
        s[threadIdx.y + 8 * i][threadIdx.x] = ip[(size_t)(threadIdx.y + 8 * i) * chS + threadIdx.x];
    __syncthreads();
    const size_t ob = ((size_t)b * H * W + (size_t)y * W + x0) * Cin + ci0;
#pragma unroll
    for (int i = 0; i < 4; i++) {
        int xl = threadIdx.y + 8 * i;
        float v = s[threadIdx.x][xl];
        __nv_bfloat16 h = __float2bfloat16(v);
        size_t a = ob + (size_t)xl * Cin + threadIdx.x;
        ph[a] = h;
        pl[a] = __float2bfloat16(v - __bfloat162float(h));
    }
}

// ---------------- weight prep ---------------------------------------------------
__global__ __launch_bounds__(256) void prep_w_kernel(
    const float* __restrict__ w, __nv_bfloat16* __restrict__ wh,
    __nv_bfloat16* __restrict__ wl, int Cout, int Cpad, int Cin, int n)
{
    int i = blockIdx.x * 256 + threadIdx.x;
    if (i >= n) return;
    int tap = i / (Cpad * Cin);
    int rem = i - tap * Cpad * Cin;
    int co = rem / Cin, ci = rem - co * Cin;
    float v = (co < Cout) ? w[((size_t)co * Cin + ci) * 9 + tap] : 0.f;
    __nv_bfloat16 h = __float2bfloat16(v);
    wh[i] = h;
    wl[i] = __float2bfloat16(v - __bfloat162float(h));
}

// ---------------- warp-MMA implicit-GEMM 3x3 conv (bf16 split) -----------------
// K rounds ordered c-outer / tap-inner for L2 reuse of B rows across taps.
// mode 0: NCHW fp32 out (+relu per doRelu==1 always here). mode 1: NHWC bf16
// hi/lo out via smem transpose (relu always; Cout==Cpad required).
template<int MT>
__global__ __launch_bounds__(256) void conv_mma_kernel(
    const __nv_bfloat16* __restrict__ Ph, const __nv_bfloat16* __restrict__ Pl,
    const __nv_bfloat16* __restrict__ Wh, const __nv_bfloat16* __restrict__ Wl,
    const float* __restrict__ bias, float* __restrict__ out,
    __nv_bfloat16* __restrict__ pho, __nv_bfloat16* __restrict__ plo, int mode,
    int Cin, int Cout, int H, int W, int logW, int logC)
{
    constexpr int ASZ = MT * 128;
    constexpr int STG = 2 * ASZ + 32768;
    constexpr int NT  = (MT == 128) ? 8 : 4;
    constexpr int LOGMT = (MT == 128) ? 7 : 6;

    extern __shared__ char smraw[];
    const uint32_t sb0 = smem_u32(smraw);
    const uint32_t sb = (sb0 + 127) & ~127u;
    char* sm = smraw + (sb - sb0);

    const int tid = threadIdx.x;
    const int wid = tid >> 5, lane = tid & 31;
    const int mbase = (MT == 128) ? ((wid & 3) << 5) : ((wid & 1) << 5);
    const int nbase = (MT == 128) ? ((wid >> 2) << 6) : ((wid >> 1) << 5);

    const int p0  = blockIdx.x << 7;
    const int b   = blockIdx.y;
    const int co0 = blockIdx.z * MT;
    const int Cpad = gridDim.z * MT;
    const int HW = H * W;
    const __nv_bfloat16* PhB = Ph + (size_t)b * HW * Cin;
    const __nv_bfloat16* PlB = Pl + (size_t)b * HW * Cin;

    float acc[2][NT][4];
#pragma unroll
    for (int mt = 0; mt < 2; mt++)
#pragma unroll
        for (int nt = 0; nt < NT; nt++)
#pragma unroll
            for (int e = 0; e < 4; e++) acc[mt][nt][e] = 0.f;

    const int R = 9 << logC;
    const int c16 = tid & 7;
    const int rg  = tid >> 3;
    const uint32_t xorv = (uint32_t)(lane & 7) << 4;
    const int matq = lane >> 3;
    const int rowA = ((matq & 1) << 3) + (lane & 7);
    const int kbA16 = (matq >> 1) << 4;
    const int rowB = ((matq >> 1) << 3) + (lane & 7);
    const int kbB16 = (matq & 1) << 4;

    auto stage = [&](int rr) {
        const uint32_t sbStg = sb + (uint32_t)(rr & 1) * STG;
        const int c = rr / 9, tap = rr - 9 * c;     // tap-inner ordering
        const int dy = tap / 3 - 1, dx = tap - (tap / 3) * 3 - 1;
#pragma unroll
        for (int k = 0; k < MT / 32; k++) {
            int row = rg + (k << 5);
            uint32_t off = (uint32_t)(row << 7) + (((uint32_t)c16 << 4) ^ (((uint32_t)(row & 7)) << 4));
            size_t gA = ((size_t)tap * Cpad + co0 + row) * Cin + (c << 6) + (c16 << 3);
            cpasync16(sbStg + off,       Wh + gA);
            cpasync16(sbStg + ASZ + off, Wl + gA);
        }
#pragma unroll
        for (int k = 0; k < 4; k++) {
            int row = rg + (k << 5);
            int p = p0 + row;
            int y = p >> logW, x = p & (W - 1);
            int yy = y + dy; yy = (yy < 0) ? 1 : ((yy >= H) ? H - 2 : yy);
            int xx = x + dx; xx = (xx < 0) ? 1 : ((xx >= W) ? W - 2 : xx);
            size_t gB = (size_t)(yy * W + xx) * Cin + (c << 6) + (c16 << 3);
            uint32_t off = (uint32_t)(row << 7) + (((uint32_t)c16 << 4) ^ (((uint32_t)(row & 7)) << 4));
            cpasync16(sbStg + 2 * ASZ + off,         PhB + gB);
            cpasync16(sbStg + 2 * ASZ + 16384 + off, PlB + gB);
        }
    };

    stage(0);
    CP_COMMIT();

    for (int r = 0; r < R; r++) {
        if (r + 1 < R) { stage(r + 1); CP_COMMIT(); CP_WAIT1(); }
        else          { CP_WAIT0(); }
        __syncthreads();

        const uint32_t base = sb + (uint32_t)(r & 1) * STG;
#pragma unroll
        for (int ks = 0; ks < 4; ks++) {
            const uint32_t kb = (uint32_t)(ks << 5);
            uint32_t ah[2][4], al[2][4];
#pragma unroll
            for (int mt = 0; mt < 2; mt++) {
                int rowm = mbase + (mt << 4) + rowA;
                uint32_t ad = base + (uint32_t)(rowm << 7) + ((kb + kbA16) ^ xorv);
                ldsm4(ah[mt][0], ah[mt][1], ah[mt][2], ah[mt][3], ad);
                ldsm4(al[mt][0], al[mt][1], al[mt][2], al[mt][3], ad + ASZ);
            }
#pragma unroll
            for (int ntp = 0; ntp < NT / 2; ntp++) {
                int rown = nbase + (ntp << 4) + rowB;
                uint32_t bd = base + 2 * ASZ + (uint32_t)(rown << 7) + ((kb + kbB16) ^ xorv);
                uint32_t bh[4], bl[4];
                ldsm4(bh[0], bh[1], bh[2], bh[3], bd);
                ldsm4(bl[0], bl[1], bl[2], bl[3], bd + 16384);
#pragma unroll
                for (int mt = 0; mt < 2; mt++) {
                    float* c0 = acc[mt][ntp * 2];
                    float* c1 = acc[mt][ntp * 2 + 1];
                    mma16816(c0, ah[mt][0], ah[mt][1], ah[mt][2], ah[mt][3], bh[0], bh[1]);
                    mma16816(c0, ah[mt][0], ah[mt][1], ah[mt][2], ah[mt][3], bl[0], bl[1]);
                    mma16816(c0, al[mt][0], al[mt][1], al[mt][2], al[mt][3], bh[0], bh[1]);
                    mma16816(c1, ah[mt][0], ah[mt][1], ah[mt][2], ah[mt][3], bh[2], bh[3]);
                    mma16816(c1, ah[mt][0], ah[mt][1], ah[mt][2], ah[mt][3], bl[2], bl[3]);
                    mma16816(c1, al[mt][0], al[mt][1], al[mt][2], al[mt][3], bh[2], bh[3]);
                }
            }
        }
        __syncthreads();
    }

    if (mode) {
        // NHWC bf16 hi/lo epilogue via smem transpose (relu; Cout==Cpad)
        float* sf = (float*)sm;
#pragma unroll
        for (int mt = 0; mt < 2; mt++)
#pragma unroll
            for (int nt = 0; nt < NT; nt++)
#pragma unroll
                for (int e = 0; e < 4; e++) {
                    int px = nbase + (nt << 3) + ((lane & 3) << 1) + (e & 1);
                    int cl = mbase + (mt << 4) + (lane >> 2) + ((e >> 1) << 3);
                    sf[px * (MT + 4) + cl] = acc[mt][nt][e];
                }
        __syncthreads();
        for (int j = tid; j < 128 * MT; j += 256) {
            int cl = j & (MT - 1), px = j >> LOGMT;
            float v = fmaxf(sf[px * (MT + 4) + cl] + bias[co0 + cl], 0.f);
            __nv_bfloat16 h = __float2bfloat16(v);
            size_t a = ((size_t)b * HW + p0 + px) * (size_t)Cout + co0 + cl;
            pho[a] = h;
            plo[a] = __float2bfloat16(v - __bfloat162float(h));
        }
    } else {
#pragma unroll
        for (int mt = 0; mt < 2; mt++)
#pragma unroll
            for (int hh = 0; hh < 2; hh++) {
                int co = co0 + mbase + (mt << 4) + (lane >> 2) + (hh << 3);
                if (co < Cout) {
                    float bv = bias[co];
                    float* op = out + (size_t)(b * Cout + co) * HW + p0 + nbase + ((lane & 3) << 1);
#pragma unroll
                    for (int nt = 0; nt < NT; nt++) {
                        float2 v;
                        v.x = fmaxf(acc[mt][nt][hh * 2]     + bv, 0.f);
                        v.y = fmaxf(acc[mt][nt][hh * 2 + 1] + bv, 0.f);
                        *(float2*)(op + (nt << 3)) = v;
                    }
                }
            }
    }
}

// ---------------- fused bilinear up2 + NHWC bf16 split -------------------------
// Grid (2W/64, 2H, B*C/32), block (32,8). Output always feeds a conv.
__global__ __launch_bounds__(256) void up2split_kernel(
    const float* __restrict__ in, __nv_bfloat16* __restrict__ ph,
    __nv_bfloat16* __restrict__ pl, int C, int Hin, int Win, int cgN)
{
    __shared__ float s[2][32][35];
    const int b = blockIdx.z / cgN, ci0 = (blockIdx.z % cgN) << 5;
    const int yo = blockIdx.y, xo0 = blockIdx.x << 6;
    const int Ho = Hin * 2, Wo = Win * 2;
    int iy = yo >> 1, y0, y1;
    float wy0, wy1;
    if (yo & 1) { y0 = iy; y1 = min(iy + 1, Hin - 1); wy0 = .75f; wy1 = .25f; }
    else        { y0 = max(iy - 1, 0); y1 = iy;       wy0 = .25f; wy1 = .75f; }
    const int xin0 = xo0 >> 1;
    const int tid = threadIdx.y * 32 + threadIdx.x;
    for (int i = tid; i < 2176; i += 256) {
        int r = i / 1088, rem = i - r * 1088;
        int ch = rem / 34, col = rem - ch * 34;
        int gc = min(max(xin0 - 1 + col, 0), Win - 1);
        int gr = r ? y1 : y0;
        s[r][ch][col] = in[((size_t)(b * C + ci0 + ch) * Hin + gr) * Win + gc];
    }
    __syncthreads();
    const int tx = threadIdx.x;
    const size_t obase = ((size_t)b * Ho + yo) * Wo;
#pragma unroll
    for (int k = 0; k < 8; k++) {
        int xo = xo0 + (k << 3) + threadIdx.y;
        int lx = (xo >> 1) - xin0;
        int ca, cb;
        float wa, wb;
        if (xo & 1) { ca = lx + 1; cb = lx + 2; wa = .75f; wb = .25f; }
        else        { ca = lx;     cb = lx + 1; wa = .25f; wb = .75f; }
        float v = wy0 * (wa * s[0][tx][ca] + wb * s[0][tx][cb])
                + wy1 * (wa * s[1][tx][ca] + wb * s[1][tx][cb]);
        __nv_bfloat16 h = __float2bfloat16(v);
        size_t a = (obase + xo) * C + ci0 + tx;
        ph[a] = h;
        pl[a] = __float2bfloat16(v - __bfloat162float(h));
    }
}

// ---------------- fp32 direct conv (final 64->3) -------------------------------
template<int CBT>
__global__ __launch_bounds__(256) void conv3x3_kernel(
    const float* __restrict__ in, const float* __restrict__ wgt,
    const float* __restrict__ bias, float* __restrict__ out,
    int Cin, int Cout, int H, int W, int tilesY, int doRelu)
{
    __shared__ __align__(16) float s_in[CCH][34][34];
    __shared__ __align__(16) float s_w[CCH][9][CBT];
    const int tx = threadIdx.x, ty = threadIdx.y;
    const int tid = ty * 32 + tx;
    const int tileY = blockIdx.y % tilesY;
    const int b = blockIdx.y / tilesY;
    const int co0 = blockIdx.z * CBT;
    const int x0 = blockIdx.x * 32, y0 = tileY * 32;
    float acc[PY][CBT];
#pragma unroll
    for (int p = 0; p < PY; p++)
#pragma unroll
        for (int j = 0; j < CBT; j++) acc[p][j] = 0.f;
    const float* inB = in + (size_t)b * Cin * H * W;
    for (int cin0 = 0; cin0 < Cin; cin0 += CCH) {
        __syncthreads();
        for (int i = tid; i < CCH * 1156; i += 256) {
            int ci = i / 1156, rem = i - ci * 1156;
            int r = rem / 34, c = rem - r * 34;
            int gr = y0 - 1 + r, gc = x0 - 1 + c;
            gr = (gr < 0) ? -gr : ((gr >= H) ? 2 * H - 2 - gr : gr);
            gc = (gc < 0) ? -gc : ((gc >= W) ? 2 * W - 2 - gc : gc);
            s_in[ci][r][c] = inB[(size_t)(cin0 + ci) * H * W + gr * W + gc];
        }
        for (int i = tid; i < CCH * 9 * CBT; i += 256) {
            int ci = i / (9 * CBT), rem = i - ci * (9 * CBT);
            int k = rem / CBT, j = rem - k * CBT;
            int co = co0 + j;
            s_w[ci][k][j] = (co < Cout) ? wgt[((size_t)co * Cin + cin0 + ci) * 9 + k] : 0.f;
        }
        __syncthreads();
#pragma unroll 1
        for (int ci = 0; ci < CCH; ci++) {
            float dp[6][3];
#pragma unroll
            for (int rr = 0; rr < 6; rr++)
#pragma unroll
                for (int c = 0; c < 3; c++) dp[rr][c] = s_in[ci][ty * PY + rr][tx + c];
#pragma unroll
            for (int kr = 0; kr < 3; kr++)
#pragma unroll
                for (int kc = 0; kc < 3; kc++) {
#pragma unroll
                    for (int p = 0; p < PY; p++) {
                        float d = dp[kr + p][kc];
#pragma unroll
                        for (int j = 0; j < CBT; j++)
                            acc[p][j] = fmaf(d, s_w[ci][kr * 3 + kc][j], acc[p][j]);
                    }
                }
        }
    }
    const int x = x0 + tx, yBase = y0 + ty * PY;
#pragma unroll
    for (int p = 0; p < PY; p++) {
        int y = yBase + p;
#pragma unroll
        for (int j = 0; j < CBT; j++) {
            int co = co0 + j;
            if (co < Cout) {
                float r = acc[p][j] + bias[co];
                if (doRelu) r = fmaxf(r, 0.f);
                out[((size_t)(b * Cout + co) * H + y) * W + x] = r;
            }
        }
    }
}

// ---------------- per-class instance-norm --------------------------------------
__global__ __launch_bounds__(256) void segnorm_stats(
    const float* __restrict__ x, const int* __restrict__ seg,
    float* __restrict__ stats, int C, int HW, int logW, int sh)
{
    const int bc = blockIdx.x, b = bc / C;
    const float* xp = x + (size_t)bc * HW;
    const int* sp = seg + b * 4096;
    const int Wm1 = (1 << logW) - 1;
    float s[8] = {0}, q[8] = {0};
    for (int i = threadIdx.x; i < HW; i += 256) {
        int h = i >> logW, wd = i & Wm1;
        int cls = sp[((h >> sh) << 6) + (wd >> sh)];
        float v = xp[i], v2 = v * v;
#pragma unroll
        for (int k = 0; k < 8; k++)
            if (cls == k) { s[k] += v; q[k] += v2; }
    }
#pragma unroll
    for (int k = 0; k < 8; k++)
#pragma unroll
        for (int o = 16; o > 0; o >>= 1) {
            s[k] += __shfl_xor_sync(0xffffffffu, s[k], o);
            q[k] += __shfl_xor_sync(0xffffffffu, q[k], o);
        }
    __shared__ float shs[8][8], shq[8][8];
    int warp = threadIdx.x >> 5, lane = threadIdx.x & 31;
    if (lane == 0)
#pragma unroll
        for (int k = 0; k < 8; k++) { shs[warp][k] = s[k]; shq[warp][k] = q[k]; }
    __syncthreads();
    if (threadIdx.x < 8) {
        float S = 0, Q = 0;
#pragma unroll
        for (int w = 0; w < 8; w++) { S += shs[w][threadIdx.x]; Q += shq[w][threadIdx.x]; }
        stats[bc * 16 + threadIdx.x * 2] = S;
        stats[bc * 16 + threadIdx.x * 2 + 1] = Q;
    }
}

__global__ __launch_bounds__(256) void segnorm_apply(
    const float* __restrict__ x, const int* __restrict__ seg,
    const float* __restrict__ stats, float* __restrict__ out,
    int C, int HW, int logW, int sh, int pxPerChunk, float invHW)
{
    const int bc = blockIdx.x, b = bc / C;
    __shared__ float s_rs[8], s_muR[8];
    if (threadIdx.x < 8) {
        float S = stats[bc * 16 + threadIdx.x * 2];
        float Q = stats[bc * 16 + threadIdx.x * 2 + 1];
        float mu = S * invHW;
        float var = Q * invHW - mu * mu;
        float r = rsqrtf(var + EPS_SN);
        s_rs[threadIdx.x] = r;
        s_muR[threadIdx.x] = mu * r;
    }
    __syncthreads();
    float K = 0.f;
#pragma unroll
    for (int k = 0; k < 8; k++) K += s_muR[k];
    const float* xp = x + (size_t)bc * HW;
    float* op = out + (size_t)bc * HW;
    const int* sp = seg + b * 4096;
    const int Wm1 = (1 << logW) - 1;
    const int end = min(HW, (int)((blockIdx.y + 1) * pxPerChunk));
    for (int i = blockIdx.y * pxPerChunk + threadIdx.x; i < end; i += 256) {
        int h = i >> logW, wd = i & Wm1;
        int cls = sp[((h >> sh) << 6) + (wd >> sh)];
        op[i] = xp[i] * s_rs[cls] - K;
    }
}

// ---------------- host orchestration -------------------------------------------
static inline int ilog2i(int v) { int l = 0; while ((1 << l) < v) l++; return l; }

#define DSMEM_128 (2 * (2 * 128 * 128 + 32768) + 128)
#define DSMEM_64  (2 * (2 * 64 * 128 + 32768) + 128)

static __nv_bfloat16 *s_wh, *s_wl;

static void conv_mma(const __nv_bfloat16* pih, const __nv_bfloat16* pil,
                     const float* w, const float* bias, float* outF,
                     __nv_bfloat16* poh, __nv_bfloat16* pol, int mode,
                     int B, int Cin, int Cout, int H, int W) {
    int MT = (Cout > 64) ? 128 : 64;
    int Cpad = ((Cout + MT - 1) / MT) * MT;
    int n = 9 * Cpad * Cin;
    prep_w_kernel<<<(n + 255) / 256, 256>>>(w, s_wh, s_wl, Cout, Cpad, Cin, n);
    if (MT == 128)
        conv_mma_kernel<128><<<dim3((H * W) / 128, B, Cpad / 128), 256, DSMEM_128>>>(
            pih, pil, s_wh, s_wl, bias, outF, poh, pol, mode, Cin, Cout, H, W,
            ilog2i(W), ilog2i(Cin / 64));
    else
        conv_mma_kernel<64><<<dim3((H * W) / 128, B, Cpad / 64), 256, DSMEM_64>>>(
            pih, pil, s_wh, s_wl, bias, outF, poh, pol, mode, Cin, Cout, H, W,
            ilog2i(W), ilog2i(Cin / 64));
}

static void launch_segnorm(const float* in, const int* seg, float* stats,
                           float* out, int B, int C, int H, int W) {
    int HW = H * W, logW = ilog2i(W), sh = ilog2i(H / 64);
    segnorm_stats<<<B * C, 256>>>(in, seg, stats, C, HW, logW, sh);
    int chunks = (HW > 16384) ? (HW >> 14) : 1;
    segnorm_apply<<<dim3(B * C, chunks), 256>>>(in, seg, stats, out, C, HW, logW,
                                                sh, HW / chunks, 1.0f / (float)HW);
}

extern "C" void kernel_launch(void* const* d_in, const int* in_sizes, int n_in,
                              void* d_out, int out_size) {
    const float* x   = (const float*)d_in[0];
    const int*   seg = (const int*)  d_in[1];
    const float *w1 = (const float*)d_in[2],  *b1 = (const float*)d_in[3];
    const float *w2 = (const float*)d_in[4],  *b2 = (const float*)d_in[5];
    const float *w3 = (const float*)d_in[6],  *b3 = (const float*)d_in[7];
    const float *w4 = (const float*)d_in[8],  *b4 = (const float*)d_in[9];
    const float *w5 = (const float*)d_in[10], *b5 = (const float*)d_in[11];
    const float *w6 = (const float*)d_in[12], *b6 = (const float*)d_in[13];
    const float *w7 = (const float*)d_in[14], *b7 = (const float*)d_in[15];
    const float *w8 = (const float*)d_in[16], *b8 = (const float*)d_in[17];
    const float *wf = (const float*)d_in[18], *bf_ = (const float*)d_in[19];

    cudaFuncSetAttribute(conv_mma_kernel<128>,
                         cudaFuncAttributeMaxDynamicSharedMemorySize, DSMEM_128);
    cudaFuncSetAttribute(conv_mma_kernel<64>,
                         cudaFuncAttributeMaxDynamicSharedMemorySize, DSMEM_64);

    float *A, *Bb, *st;
    __nv_bfloat16 *p0h, *p0l, *p1h, *p1l;
    cudaGetSymbolAddress((void**)&A,   g_bufA);
    cudaGetSymbolAddress((void**)&Bb,  g_bufB);
    cudaGetSymbolAddress((void**)&st,  g_stats);
    cudaGetSymbolAddress((void**)&p0h, g_P0h);
    cudaGetSymbolAddress((void**)&p0l, g_P0l);
    cudaGetSymbolAddress((void**)&p1h, g_P1h);
    cudaGetSymbolAddress((void**)&p1l, g_P1l);
    cudaGetSymbolAddress((void**)&s_wh, g_Wh);
    cudaGetSymbolAddress((void**)&s_wl, g_Wl);

    // stage 1 @ 64x64
    nchw_split_kernel<<<dim3(2, 64, 4 * 16), dim3(32, 8)>>>(x, p0h, p0l, 512, 64, 64, 16);
    conv_mma(p0h, p0l, w1, b1, A, 0, 0, 0, 4, 512, 256, 64, 64);
    launch_segnorm(A, seg, st, Bb, 4, 256, 64, 64);
    up2split_kernel<<<dim3(2, 128, 4 * 8), dim3(32, 8)>>>(Bb, p1h, p1l, 256, 64, 64, 8);
    // stage 2 @ 128x128
    conv_mma(p1h, p1l, w2, b2, 0, p0h, p0l, 1, 4, 256, 256, 128, 128);
    conv_mma(p0h, p0l, w3, b3, 0, p1h, p1l, 1, 4, 256, 256, 128, 128);
    conv_mma(p1h, p1l, w4, b4, 0, p0h, p0l, 1, 4, 256, 256, 128, 128);
    conv_mma(p0h, p0l, w5, b5, A, 0, 0, 0, 4, 256, 128, 128, 128);
    launch_segnorm(A, seg, st, Bb, 4, 128, 128, 128);
    up2split_kernel<<<dim3(4, 256, 4 * 4), dim3(32, 8)>>>(Bb, p1h, p1l, 128, 128, 128, 4);
    // stage 3 @ 256x256
    conv_mma(p1h, p1l, w6, b6, 0, p0h, p0l, 1, 4, 128, 128, 256, 256);
    conv_mma(p0h, p0l, w7, b7, A, 0, 0, 0, 4, 128, 64, 256, 256);
    launch_segnorm(A, seg, st, Bb, 4, 64, 256, 256);
    up2split_kernel<<<dim3(8, 512, 4 * 2), dim3(32, 8)>>>(Bb, p1h, p1l, 64, 256, 256, 2);
    // stage 4 @ 512x512
    conv_mma(p1h, p1l, w8, b8, Bb, 0, 0, 0, 4, 64, 64, 512, 512);
    conv3x3_kernel<4><<<dim3(16, 16 * 4, 1), dim3(32, 8)>>>(
        Bb, wf, bf_, (float*)d_out, 64, 3, 512, 512, 16, 0);
}